// round 7
// baseline (speedup 1.0000x reference)
#include <cuda_runtime.h>
#include <cuda_fp16.h>
#include <math_constants.h>

// Problem constants (fixed by the reference)
#define NN     20000
#define EE     640000
#define ETOT   (EE + NN)      // edges + self loops
#define INF_C  256
#define HEADS  8
#define HF1    64
#define OUT2   32
#define NEG_SLOPE 0.2f

// ---------------- static scratch (no allocations allowed) ----------------
__device__ __half g_xh  [NN * INF_C];         // x in fp16
__device__ __half g_W1h [INF_C * HEADS * HF1];
__device__ __half g_W2h [HF1 * HEADS * OUT2];
__device__ __half g_h1  [NN * HEADS * HF1];   // layer1 projected features (fp16)
__device__ __half g_hmid[NN * HF1];           // layer1 output (fp16, feeds GEMM2)
__device__ __half g_h2  [NN * HEADS * OUT2];  // layer2 projected features (fp16)
__device__ __align__(16) float g_as1 [NN * HEADS];
__device__ __align__(16) float g_ad1 [NN * HEADS];
__device__ __align__(16) float g_as2 [NN * HEADS];
__device__ __align__(16) float g_ad2 [NN * HEADS];
__device__ int   g_deg [NN];
__device__ int   g_off [NN + 1];
__device__ int   g_cur [NN];
__device__ int   g_csr [ETOT];               // src node of each edge, grouped by dst

// ---------------- fp32 -> fp16 conversion ----------------
__global__ void f2h_kernel(const float* __restrict__ src, __half* __restrict__ dst, int n4) {
    int i = blockIdx.x * blockDim.x + threadIdx.x;
    if (i < n4) {
        float4 v = ((const float4*)src)[i];
        ((half2*)dst)[2 * i]     = __floats2half2_rn(v.x, v.y);
        ((half2*)dst)[2 * i + 1] = __floats2half2_rn(v.z, v.w);
    }
}

// ---------------- CSR build ----------------
__global__ void count_deg_kernel(const int* __restrict__ ei) {
    int e = blockIdx.x * blockDim.x + threadIdx.x;
    if (e < EE) atomicAdd(&g_deg[ei[EE + e]], 1);
}

// exclusive scan of (deg + 1 self-loop); also initializes cursor array
__global__ void scan_kernel() {
    __shared__ int warpsum[32];
    __shared__ int carry_s;
    const int tid = threadIdx.x, lane = tid & 31, wid = tid >> 5;
    if (tid == 0) carry_s = 0;
    __syncthreads();
    for (int base = 0; base < NN; base += 1024) {
        int i = base + tid;
        int v = (i < NN) ? (g_deg[i] + 1) : 0;   // +1 = self loop
        int x = v;
        #pragma unroll
        for (int o = 1; o < 32; o <<= 1) {
            int y = __shfl_up_sync(0xFFFFFFFFu, x, o);
            if (lane >= o) x += y;
        }
        if (lane == 31) warpsum[wid] = x;
        __syncthreads();
        if (wid == 0) {
            int s = warpsum[lane];
            #pragma unroll
            for (int o = 1; o < 32; o <<= 1) {
                int y = __shfl_up_sync(0xFFFFFFFFu, s, o);
                if (lane >= o) s += y;
            }
            warpsum[lane] = s;
        }
        __syncthreads();
        int woff = wid ? warpsum[wid - 1] : 0;
        int excl = carry_s + woff + x - v;
        if (i < NN) { g_off[i] = excl; g_cur[i] = excl; }
        int total = warpsum[31];
        __syncthreads();
        if (tid == 0) carry_s += total;
        __syncthreads();
    }
    if (threadIdx.x == 0) g_off[NN] = carry_s;
}

__global__ void fill_csr_kernel(const int* __restrict__ ei) {
    int idx = blockIdx.x * blockDim.x + threadIdx.x;
    if (idx < EE) {
        int s = ei[idx];
        int d = ei[EE + idx];
        int pos = atomicAdd(&g_cur[d], 1);
        g_csr[pos] = s;
    } else if (idx < ETOT) {
        int i = idx - EE;
        int pos = atomicAdd(&g_cur[i], 1);
        g_csr[pos] = i;   // self loop
    }
}

// ---------------- fp16-input tensor-core GEMM, fp16 output ----------------
// C[M,ND] = A[M,KD] @ B[KD,ND]. mma.sync.m16n8k16 f16 (f32 accum).
// BM=128, BN=128, BK=32, 256 threads (8 warps, 4x2, 32x64 warp tile).
// ldmatrix fragment loads, register-prefetch double buffering.
// KD%32==0, ND%128==0. A rows beyond M read as zero.

__device__ __forceinline__ unsigned smaddr(const void* p) {
    return (unsigned)__cvta_generic_to_shared(p);
}

template<int KD, int ND>
__global__ __launch_bounds__(256)
void h16_gemm_kernel(int M, const __half* __restrict__ A,
                     const __half* __restrict__ B, __half* __restrict__ C) {
    constexpr int BM = 128, BN = 128, BK = 32;
    constexpr int KT = KD / BK;
    __shared__ __half As[2][BM][BK + 8];   // row stride 80B (5*16B, odd) -> ldmatrix conflict-free
    __shared__ __half Bs[2][BK][BN + 8];   // row stride 272B (17*16B, odd)
    const int tid  = threadIdx.x;
    const int lane = tid & 31;
    const int warp = tid >> 5;
    const int wm = warp >> 1;              // 0..3
    const int wn = warp & 1;               // 0..1
    const int rowBase = blockIdx.y * BM;
    const int colBase = blockIdx.x * BN;

    float c[2][8][4];
    #pragma unroll
    for (int mf = 0; mf < 2; mf++)
        #pragma unroll
        for (int nf = 0; nf < 8; nf++)
            #pragma unroll
            for (int i = 0; i < 4; i++) c[mf][nf][i] = 0.f;

    const int ar = tid >> 2;               // 0..63 (+64)
    const int ac = (tid & 3) * 8;          // 0..24
    const int br = tid >> 4;               // 0..15 (+16)
    const int bc = (tid & 15) * 8;         // 0..120
    const int g  = lane >> 2;
    const int tg = lane & 3;

    uint4 aL[2], bL[2];
    const uint4 zero4 = make_uint4(0u, 0u, 0u, 0u);

    auto gload = [&](int it) {
        const int k0 = it * BK;
        #pragma unroll
        for (int i = 0; i < 2; i++) {
            int r = rowBase + ar + i * 64;
            aL[i] = (r < M) ? *(const uint4*)&A[(size_t)r * KD + k0 + ac] : zero4;
        }
        #pragma unroll
        for (int j = 0; j < 2; j++)
            bL[j] = *(const uint4*)&B[(size_t)(k0 + br + j * 16) * ND + colBase + bc];
    };
    auto sstore = [&](int buf) {
        #pragma unroll
        for (int i = 0; i < 2; i++)
            *(uint4*)&As[buf][ar + i * 64][ac] = aL[i];
        #pragma unroll
        for (int j = 0; j < 2; j++)
            *(uint4*)&Bs[buf][br + j * 16][bc] = bL[j];
    };
    auto compute = [&](int buf) {
        #pragma unroll
        for (int ks = 0; ks < 2; ks++) {
            unsigned a[2][4], b[8][2];
            #pragma unroll
            for (int mf = 0; mf < 2; mf++) {
                unsigned ad = smaddr(&As[buf][wm * 32 + mf * 16 + (lane & 15)]
                                            [ks * 16 + ((lane >> 4) & 1) * 8]);
                asm volatile(
                    "ldmatrix.sync.aligned.m8n8.x4.shared.b16 {%0,%1,%2,%3}, [%4];"
                    : "=r"(a[mf][0]), "=r"(a[mf][1]), "=r"(a[mf][2]), "=r"(a[mf][3])
                    : "r"(ad));
            }
            #pragma unroll
            for (int nq = 0; nq < 4; nq++) {
                unsigned ad = smaddr(&Bs[buf][ks * 16 + (lane & 15)]
                                            [wn * 64 + nq * 16 + ((lane >> 4) & 1) * 8]);
                asm volatile(
                    "ldmatrix.sync.aligned.m8n8.x4.trans.shared.b16 {%0,%1,%2,%3}, [%4];"
                    : "=r"(b[nq * 2][0]), "=r"(b[nq * 2][1]),
                      "=r"(b[nq * 2 + 1][0]), "=r"(b[nq * 2 + 1][1])
                    : "r"(ad));
            }
            #pragma unroll
            for (int mf = 0; mf < 2; mf++)
                #pragma unroll
                for (int nf = 0; nf < 8; nf++)
                    asm volatile(
                        "mma.sync.aligned.m16n8k16.row.col.f32.f16.f16.f32 "
                        "{%0,%1,%2,%3}, {%4,%5,%6,%7}, {%8,%9}, {%0,%1,%2,%3};"
                        : "+f"(c[mf][nf][0]), "+f"(c[mf][nf][1]),
                          "+f"(c[mf][nf][2]), "+f"(c[mf][nf][3])
                        : "r"(a[mf][0]), "r"(a[mf][1]), "r"(a[mf][2]), "r"(a[mf][3]),
                          "r"(b[nf][0]), "r"(b[nf][1]));
        }
    };

    gload(0);
    sstore(0);
    __syncthreads();
    #pragma unroll
    for (int it = 0; it < KT; it++) {
        if (it + 1 < KT) gload(it + 1);      // overlap gmem loads with compute
        compute(it & 1);
        __syncthreads();
        if (it + 1 < KT) {
            sstore((it + 1) & 1);
            __syncthreads();
        }
    }

    #pragma unroll
    for (int mf = 0; mf < 2; mf++) {
        #pragma unroll
        for (int nf = 0; nf < 8; nf++) {
            int col = colBase + wn * 64 + nf * 8 + tg * 2;
            int r0 = rowBase + wm * 32 + mf * 16 + g;
            if (r0 < M)
                *(half2*)&C[(size_t)r0 * ND + col] = __floats2half2_rn(c[mf][nf][0], c[mf][nf][1]);
            int r1 = r0 + 8;
            if (r1 < M)
                *(half2*)&C[(size_t)r1 * ND + col] = __floats2half2_rn(c[mf][nf][2], c[mf][nf][3]);
        }
    }
}

// ---------------- per-node attention logits (fp16 features) ----------------
// blockDim = 4*CH (one half2 per thread)
template<int CH>
__global__ void attn_logits_kernel(const __half* __restrict__ h,
                                   const float* __restrict__ att_s,
                                   const float* __restrict__ att_d,
                                   float* __restrict__ asrc,
                                   float* __restrict__ adst) {
    const int n = blockIdx.x;
    const int t = threadIdx.x;
    float2 v = __half22float2(((const half2*)h)[(size_t)n * (4 * CH) + t]);
    float ps = v.x * att_s[2 * t] + v.y * att_s[2 * t + 1];
    float pd = v.x * att_d[2 * t] + v.y * att_d[2 * t + 1];
    constexpr int LPH = CH / 2;   // lanes per head
    #pragma unroll
    for (int o = LPH / 2; o; o >>= 1) {
        ps += __shfl_xor_sync(0xFFFFFFFFu, ps, o);
        pd += __shfl_xor_sync(0xFFFFFFFFu, pd, o);
    }
    if ((t & (LPH - 1)) == 0) {
        int hh = t / LPH;
        asrc[n * 8 + hh] = ps;
        adst[n * 8 + hh] = pd;
    }
}

// ---------------- GAT aggregation: warp-per-head, single pass, no block syncs ----------
// alpha = exp(e)/sum(exp(e)) (no max-sub needed; |e| small). Each warp owns one
// head: loads 32-edge batches of csr coalesced, computes 32 weights (one exp
// instr), broadcasts (s,w) via shfl in the gather loop. Per-head denominator by
// warp reduction. One __syncthreads total (head-mean).
template<int CH, typename OutT>
__global__ __launch_bounds__(256)
void gat_aggregate_kernel(const __half* __restrict__ h,
                          const float* __restrict__ asrc,
                          const float* __restrict__ adst,
                          const float* __restrict__ bias,
                          OutT* __restrict__ out,
                          int do_relu) {
    const int d = blockIdx.x;
    const int t = threadIdx.x;
    const int lane = t & 31;
    const int hh = t >> 5;                 // warp = head
    const int start = g_off[d];
    const int deg = g_off[d + 1] - start;
    constexpr int HP  = CH / 2;            // half2 per head row (32 or 16)
    constexpr int EPW = 32 / HP;           // edges per inner step (1 or 2)
    const int sub = lane / HP;             // which edge of the pair
    const int cp  = lane % HP;             // channel pair

    const float ad = adst[d * 8 + hh];
    const half2* __restrict__ h2p = (const half2*)h;
    float2 acc = make_float2(0.f, 0.f);
    float den = 0.f;

    for (int j0 = 0; j0 < deg; j0 += 32) {
        int j = j0 + lane;
        int sv = 0;
        float wl = 0.f;
        if (j < deg) {
            sv = g_csr[start + j];
            float e = asrc[sv * 8 + hh] + ad;
            e = (e > 0.f) ? e : NEG_SLOPE * e;
            wl = __expf(e);
            den += wl;
        }
        const int lim = min(32, deg - j0);
        #pragma unroll 4
        for (int k = 0; k < lim; k += EPW) {
            int   s = __shfl_sync(0xFFFFFFFFu, sv, k + sub);
            float w = __shfl_sync(0xFFFFFFFFu, wl, k + sub);
            float2 v = __half22float2(h2p[(size_t)s * (4 * CH) + hh * HP + cp]);
            acc.x = fmaf(w, v.x, acc.x);
            acc.y = fmaf(w, v.y, acc.y);
        }
    }

    // per-head denominator: full-warp reduce (each lane held distinct edges)
    #pragma unroll
    for (int o = 16; o; o >>= 1) den += __shfl_xor_sync(0xFFFFFFFFu, den, o);
    const float is = 1.0f / den;
    acc.x *= is;
    acc.y *= is;
    if (EPW == 2) {   // combine the two edge-sublanes holding the same channels
        acc.x += __shfl_xor_sync(0xFFFFFFFFu, acc.x, 16);
        acc.y += __shfl_xor_sync(0xFFFFFFFFu, acc.y, 16);
    }

    __shared__ float s_red[8][CH];
    if (sub == 0) {
        s_red[hh][2 * cp]     = acc.x;
        s_red[hh][2 * cp + 1] = acc.y;
    }
    __syncthreads();
    if (t < CH) {
        float v = 0.f;
        #pragma unroll
        for (int k = 0; k < 8; k++) v += s_red[k][t];
        v = v * 0.125f + bias[t];
        if (do_relu) v = fmaxf(v, 0.f);
        if constexpr (sizeof(OutT) == 2)
            out[(size_t)d * CH + t] = __float2half(v);
        else
            out[(size_t)d * CH + t] = v;
    }
}

// ---------------- launch ----------------
extern "C" void kernel_launch(void* const* d_in, const int* in_sizes, int n_in,
                              void* d_out, int out_size) {
    const float* x    = (const float*)d_in[0];
    const int*   ei   = (const int*)  d_in[1];
    const float* W1   = (const float*)d_in[2];
    const float* as1  = (const float*)d_in[3];
    const float* ad1  = (const float*)d_in[4];
    const float* b1   = (const float*)d_in[5];
    const float* W2   = (const float*)d_in[6];
    const float* as2  = (const float*)d_in[7];
    const float* ad2  = (const float*)d_in[8];
    const float* b2   = (const float*)d_in[9];
    float* out = (float*)d_out;

    __half *p_xh, *p_W1h, *p_W2h, *p_h1, *p_hmid, *p_h2;
    float *p_as1, *p_ad1, *p_as2, *p_ad2;
    int *p_deg;
    cudaGetSymbolAddress((void**)&p_xh,   g_xh);
    cudaGetSymbolAddress((void**)&p_W1h,  g_W1h);
    cudaGetSymbolAddress((void**)&p_W2h,  g_W2h);
    cudaGetSymbolAddress((void**)&p_h1,   g_h1);
    cudaGetSymbolAddress((void**)&p_hmid, g_hmid);
    cudaGetSymbolAddress((void**)&p_h2,   g_h2);
    cudaGetSymbolAddress((void**)&p_as1,  g_as1);
    cudaGetSymbolAddress((void**)&p_ad1,  g_ad1);
    cudaGetSymbolAddress((void**)&p_as2,  g_as2);
    cudaGetSymbolAddress((void**)&p_ad2,  g_ad2);
    cudaGetSymbolAddress((void**)&p_deg,  g_deg);

    // fp16 conversions (independent of CSR build)
    f2h_kernel<<<(NN * INF_C / 4 + 255) / 256, 256>>>(x, p_xh, NN * INF_C / 4);
    f2h_kernel<<<(INF_C * HEADS * HF1 / 4 + 255) / 256, 256>>>(W1, p_W1h, INF_C * HEADS * HF1 / 4);
    f2h_kernel<<<(HF1 * HEADS * OUT2 / 4 + 255) / 256, 256>>>(W2, p_W2h, HF1 * HEADS * OUT2 / 4);

    // CSR build
    cudaMemsetAsync(p_deg, 0, NN * sizeof(int));
    count_deg_kernel<<<(EE + 255) / 256, 256>>>(ei);
    scan_kernel<<<1, 1024>>>();
    fill_csr_kernel<<<(ETOT + 255) / 256, 256>>>(ei);

    // Layer 1
    {
        dim3 grid((HEADS * HF1) / 128, (NN + 127) / 128);
        h16_gemm_kernel<INF_C, HEADS * HF1><<<grid, 256>>>(NN, p_xh, p_W1h, p_h1);
    }
    attn_logits_kernel<HF1><<<NN, 4 * HF1>>>(p_h1, as1, ad1, p_as1, p_ad1);
    gat_aggregate_kernel<HF1, __half><<<NN, 256>>>(p_h1, p_as1, p_ad1, b1, p_hmid, 1);

    // Layer 2
    {
        dim3 grid((HEADS * OUT2) / 128, (NN + 127) / 128);
        h16_gemm_kernel<HF1, HEADS * OUT2><<<grid, 256>>>(NN, p_hmid, p_W2h, p_h2);
    }
    attn_logits_kernel<OUT2><<<NN, 4 * OUT2>>>(p_h2, as2, ad2, p_as2, p_ad2);
    gat_aggregate_kernel<OUT2, float><<<NN, 256>>>(p_h2, p_as2, p_ad2, b2, out, 0);
}

// round 8
// speedup vs baseline: 1.0955x; 1.0955x over previous
#include <cuda_runtime.h>
#include <cuda_fp16.h>
#include <math_constants.h>

// Problem constants (fixed by the reference)
#define NN     20000
#define EE     640000
#define ETOT   (EE + NN)      // edges + self loops
#define INF_C  256
#define HEADS  8
#define HF1    64
#define OUT2   32
#define NEG_SLOPE 0.2f
#define CHUNK  128

// ---------------- static scratch (no allocations allowed) ----------------
__device__ __half g_xh  [NN * INF_C];         // x in fp16
__device__ __half g_W1h [INF_C * HEADS * HF1];
__device__ __half g_W2h [HF1 * HEADS * OUT2];
__device__ __half g_h1  [NN * HEADS * HF1];   // layer1 projected features (fp16)
__device__ __half g_hmid[NN * HF1];           // layer1 output (fp16, feeds GEMM2)
__device__ __half g_h2  [NN * HEADS * OUT2];  // layer2 projected features (fp16)
__device__ __align__(16) float g_as1 [NN * HEADS];
__device__ __align__(16) float g_ad1 [NN * HEADS];
__device__ __align__(16) float g_as2 [NN * HEADS];
__device__ __align__(16) float g_ad2 [NN * HEADS];
__device__ int   g_deg [NN];
__device__ int   g_off [NN + 1];
__device__ int   g_cur [NN];
__device__ int   g_csr [ETOT];               // src node of each edge, grouped by dst

// ---------------- fp32 -> fp16 conversion ----------------
__global__ void f2h_kernel(const float* __restrict__ src, __half* __restrict__ dst, int n4) {
    int i = blockIdx.x * blockDim.x + threadIdx.x;
    if (i < n4) {
        float4 v = ((const float4*)src)[i];
        ((half2*)dst)[2 * i]     = __floats2half2_rn(v.x, v.y);
        ((half2*)dst)[2 * i + 1] = __floats2half2_rn(v.z, v.w);
    }
}

// ---------------- CSR build ----------------
__global__ void count_deg_kernel(const int* __restrict__ ei) {
    int e = blockIdx.x * blockDim.x + threadIdx.x;
    if (e < EE) atomicAdd(&g_deg[ei[EE + e]], 1);
}

// exclusive scan of (deg + 1 self-loop); also initializes cursor array
__global__ void scan_kernel() {
    __shared__ int warpsum[32];
    __shared__ int carry_s;
    const int tid = threadIdx.x, lane = tid & 31, wid = tid >> 5;
    if (tid == 0) carry_s = 0;
    __syncthreads();
    for (int base = 0; base < NN; base += 1024) {
        int i = base + tid;
        int v = (i < NN) ? (g_deg[i] + 1) : 0;   // +1 = self loop
        int x = v;
        #pragma unroll
        for (int o = 1; o < 32; o <<= 1) {
            int y = __shfl_up_sync(0xFFFFFFFFu, x, o);
            if (lane >= o) x += y;
        }
        if (lane == 31) warpsum[wid] = x;
        __syncthreads();
        if (wid == 0) {
            int s = warpsum[lane];
            #pragma unroll
            for (int o = 1; o < 32; o <<= 1) {
                int y = __shfl_up_sync(0xFFFFFFFFu, s, o);
                if (lane >= o) s += y;
            }
            warpsum[lane] = s;
        }
        __syncthreads();
        int woff = wid ? warpsum[wid - 1] : 0;
        int excl = carry_s + woff + x - v;
        if (i < NN) { g_off[i] = excl; g_cur[i] = excl; }
        int total = warpsum[31];
        __syncthreads();
        if (tid == 0) carry_s += total;
        __syncthreads();
    }
    if (threadIdx.x == 0) g_off[NN] = carry_s;
}

__global__ void fill_csr_kernel(const int* __restrict__ ei) {
    int idx = blockIdx.x * blockDim.x + threadIdx.x;
    if (idx < EE) {
        int s = ei[idx];
        int d = ei[EE + idx];
        int pos = atomicAdd(&g_cur[d], 1);
        g_csr[pos] = s;
    } else if (idx < ETOT) {
        int i = idx - EE;
        int pos = atomicAdd(&g_cur[i], 1);
        g_csr[pos] = i;   // self loop
    }
}

// ---------------- fp16-input tensor-core GEMM, fp16 output ----------------
// C[M,ND] = A[M,KD] @ B[KD,ND]. mma.sync.m16n8k16 f16 (f32 accum).
// BM=128, BN=128, BK=32, 256 threads (8 warps, 4x2, 32x64 warp tile).
// ldmatrix fragment loads, register-prefetch double buffering.
// KD%32==0, ND%128==0. A rows beyond M read as zero.

__device__ __forceinline__ unsigned smaddr(const void* p) {
    return (unsigned)__cvta_generic_to_shared(p);
}

template<int KD, int ND>
__global__ __launch_bounds__(256)
void h16_gemm_kernel(int M, const __half* __restrict__ A,
                     const __half* __restrict__ B, __half* __restrict__ C) {
    constexpr int BM = 128, BN = 128, BK = 32;
    constexpr int KT = KD / BK;
    __shared__ __half As[2][BM][BK + 8];   // row stride 80B (5*16B, odd) -> ldmatrix conflict-free
    __shared__ __half Bs[2][BK][BN + 8];   // row stride 272B (17*16B, odd)
    const int tid  = threadIdx.x;
    const int lane = tid & 31;
    const int warp = tid >> 5;
    const int wm = warp >> 1;              // 0..3
    const int wn = warp & 1;               // 0..1
    const int rowBase = blockIdx.y * BM;
    const int colBase = blockIdx.x * BN;

    float c[2][8][4];
    #pragma unroll
    for (int mf = 0; mf < 2; mf++)
        #pragma unroll
        for (int nf = 0; nf < 8; nf++)
            #pragma unroll
            for (int i = 0; i < 4; i++) c[mf][nf][i] = 0.f;

    const int ar = tid >> 2;               // 0..63 (+64)
    const int ac = (tid & 3) * 8;          // 0..24
    const int br = tid >> 4;               // 0..15 (+16)
    const int bc = (tid & 15) * 8;         // 0..120
    const int g  = lane >> 2;
    const int tg = lane & 3;

    uint4 aL[2], bL[2];
    const uint4 zero4 = make_uint4(0u, 0u, 0u, 0u);

    auto gload = [&](int it) {
        const int k0 = it * BK;
        #pragma unroll
        for (int i = 0; i < 2; i++) {
            int r = rowBase + ar + i * 64;
            aL[i] = (r < M) ? *(const uint4*)&A[(size_t)r * KD + k0 + ac] : zero4;
        }
        #pragma unroll
        for (int j = 0; j < 2; j++)
            bL[j] = *(const uint4*)&B[(size_t)(k0 + br + j * 16) * ND + colBase + bc];
    };
    auto sstore = [&](int buf) {
        #pragma unroll
        for (int i = 0; i < 2; i++)
            *(uint4*)&As[buf][ar + i * 64][ac] = aL[i];
        #pragma unroll
        for (int j = 0; j < 2; j++)
            *(uint4*)&Bs[buf][br + j * 16][bc] = bL[j];
    };
    auto compute = [&](int buf) {
        #pragma unroll
        for (int ks = 0; ks < 2; ks++) {
            unsigned a[2][4], b[8][2];
            #pragma unroll
            for (int mf = 0; mf < 2; mf++) {
                unsigned ad = smaddr(&As[buf][wm * 32 + mf * 16 + (lane & 15)]
                                            [ks * 16 + ((lane >> 4) & 1) * 8]);
                asm volatile(
                    "ldmatrix.sync.aligned.m8n8.x4.shared.b16 {%0,%1,%2,%3}, [%4];"
                    : "=r"(a[mf][0]), "=r"(a[mf][1]), "=r"(a[mf][2]), "=r"(a[mf][3])
                    : "r"(ad));
            }
            #pragma unroll
            for (int nq = 0; nq < 4; nq++) {
                unsigned ad = smaddr(&Bs[buf][ks * 16 + (lane & 15)]
                                            [wn * 64 + nq * 16 + ((lane >> 4) & 1) * 8]);
                asm volatile(
                    "ldmatrix.sync.aligned.m8n8.x4.trans.shared.b16 {%0,%1,%2,%3}, [%4];"
                    : "=r"(b[nq * 2][0]), "=r"(b[nq * 2][1]),
                      "=r"(b[nq * 2 + 1][0]), "=r"(b[nq * 2 + 1][1])
                    : "r"(ad));
            }
            #pragma unroll
            for (int mf = 0; mf < 2; mf++)
                #pragma unroll
                for (int nf = 0; nf < 8; nf++)
                    asm volatile(
                        "mma.sync.aligned.m16n8k16.row.col.f32.f16.f16.f32 "
                        "{%0,%1,%2,%3}, {%4,%5,%6,%7}, {%8,%9}, {%0,%1,%2,%3};"
                        : "+f"(c[mf][nf][0]), "+f"(c[mf][nf][1]),
                          "+f"(c[mf][nf][2]), "+f"(c[mf][nf][3])
                        : "r"(a[mf][0]), "r"(a[mf][1]), "r"(a[mf][2]), "r"(a[mf][3]),
                          "r"(b[nf][0]), "r"(b[nf][1]));
        }
    };

    gload(0);
    sstore(0);
    __syncthreads();
    #pragma unroll
    for (int it = 0; it < KT; it++) {
        if (it + 1 < KT) gload(it + 1);      // overlap gmem loads with compute
        compute(it & 1);
        __syncthreads();
        if (it + 1 < KT) {
            sstore((it + 1) & 1);
            __syncthreads();
        }
    }

    #pragma unroll
    for (int mf = 0; mf < 2; mf++) {
        #pragma unroll
        for (int nf = 0; nf < 8; nf++) {
            int col = colBase + wn * 64 + nf * 8 + tg * 2;
            int r0 = rowBase + wm * 32 + mf * 16 + g;
            if (r0 < M)
                *(half2*)&C[(size_t)r0 * ND + col] = __floats2half2_rn(c[mf][nf][0], c[mf][nf][1]);
            int r1 = r0 + 8;
            if (r1 < M)
                *(half2*)&C[(size_t)r1 * ND + col] = __floats2half2_rn(c[mf][nf][2], c[mf][nf][3]);
        }
    }
}

// ---------------- per-node attention logits (fp16 features) ----------------
// blockDim = 4*CH (one half2 per thread)
template<int CH>
__global__ void attn_logits_kernel(const __half* __restrict__ h,
                                   const float* __restrict__ att_s,
                                   const float* __restrict__ att_d,
                                   float* __restrict__ asrc,
                                   float* __restrict__ adst) {
    const int n = blockIdx.x;
    const int t = threadIdx.x;
    float2 v = __half22float2(((const half2*)h)[(size_t)n * (4 * CH) + t]);
    float ps = v.x * att_s[2 * t] + v.y * att_s[2 * t + 1];
    float pd = v.x * att_d[2 * t] + v.y * att_d[2 * t + 1];
    constexpr int LPH = CH / 2;   // lanes per head
    #pragma unroll
    for (int o = LPH / 2; o; o >>= 1) {
        ps += __shfl_xor_sync(0xFFFFFFFFu, ps, o);
        pd += __shfl_xor_sync(0xFFFFFFFFu, pd, o);
    }
    if ((t & (LPH - 1)) == 0) {
        int hh = t / LPH;
        asrc[n * 8 + hh] = ps;
        adst[n * 8 + hh] = pd;
    }
}

// ---------------- GAT aggregation: single-pass unnormalized softmax ----------------
// alpha = exp(e)/sum(exp(e)) (no max-sub needed; |e| small). Accumulate with
// unnormalized w=exp(e), track per-head denominator, scale at the end.
// one block per dst node, blockDim = 4*CH (half2 per thread).
template<int CH, typename OutT>
__global__ void gat_aggregate_kernel(const __half* __restrict__ h,
                                     const float* __restrict__ asrc,
                                     const float* __restrict__ adst,
                                     const float* __restrict__ bias,
                                     OutT* __restrict__ out,
                                     int do_relu) {
    constexpr int NT = 4 * CH;     // 256 or 128 threads
    const int d = blockIdx.x;
    const int t = threadIdx.x;
    const int start = g_off[d];
    const int deg = g_off[d + 1] - start;

    __shared__ float sm_adst[8], sm_is[8];
    __shared__ int   s_src[CHUNK];
    __shared__ float s_w[CHUNK * 8];
    __shared__ float s_dp[NT];
    __shared__ float s_red[8 * CH];

    if (t < 8) sm_adst[t] = adst[d * 8 + t];
    __syncthreads();

    const int hh = t / (CH / 2);
    const int cp = t % (CH / 2);
    const half2* __restrict__ h2p = (const half2*)h;
    float2 acc = make_float2(0.f, 0.f);
    float denp = 0.f;

    for (int base = 0; base < deg; base += CHUNK) {
        const int cnt = min(CHUNK, deg - base);
        if (t < cnt) s_src[t] = g_csr[start + base + t];
        __syncthreads();
        // weights: thread t handles head (t&7) entries -> per-thread den partial
        for (int idx = t; idx < cnt * 8; idx += NT) {
            int j = idx >> 3, h2 = idx & 7;
            int s = s_src[j];
            float e = asrc[s * 8 + h2] + sm_adst[h2];
            e = (e > 0.f) ? e : NEG_SLOPE * e;
            float w = __expf(e);
            s_w[idx] = w;
            denp += w;
        }
        __syncthreads();
        #pragma unroll 4
        for (int j = 0; j < cnt; j++) {
            float w = s_w[j * 8 + hh];
            float2 v = __half22float2(h2p[(size_t)s_src[j] * (4 * CH) + hh * (CH / 2) + cp]);
            acc.x = fmaf(w, v.x, acc.x);
            acc.y = fmaf(w, v.y, acc.y);
        }
        __syncthreads();
    }

    // reduce per-head denominators (thread t contributed to head t&7)
    s_dp[t] = denp;
    __syncthreads();
    if (t < 8) {
        float tot = 0.f;
        #pragma unroll
        for (int k = t; k < NT; k += 8) tot += s_dp[k];
        sm_is[t] = 1.0f / tot;
    }
    __syncthreads();

    const float is = sm_is[hh];
    s_red[hh * CH + 2 * cp]     = acc.x * is;
    s_red[hh * CH + 2 * cp + 1] = acc.y * is;
    __syncthreads();
    if (t < CH) {
        float v = 0.f;
        #pragma unroll
        for (int k = 0; k < 8; k++) v += s_red[k * CH + t];
        v = v * 0.125f + bias[t];
        if (do_relu) v = fmaxf(v, 0.f);
        if constexpr (sizeof(OutT) == 2)
            out[(size_t)d * CH + t] = __float2half(v);
        else
            out[(size_t)d * CH + t] = v;
    }
}

// ---------------- launch ----------------
extern "C" void kernel_launch(void* const* d_in, const int* in_sizes, int n_in,
                              void* d_out, int out_size) {
    const float* x    = (const float*)d_in[0];
    const int*   ei   = (const int*)  d_in[1];
    const float* W1   = (const float*)d_in[2];
    const float* as1  = (const float*)d_in[3];
    const float* ad1  = (const float*)d_in[4];
    const float* b1   = (const float*)d_in[5];
    const float* W2   = (const float*)d_in[6];
    const float* as2  = (const float*)d_in[7];
    const float* ad2  = (const float*)d_in[8];
    const float* b2   = (const float*)d_in[9];
    float* out = (float*)d_out;

    __half *p_xh, *p_W1h, *p_W2h, *p_h1, *p_hmid, *p_h2;
    float *p_as1, *p_ad1, *p_as2, *p_ad2;
    int *p_deg;
    cudaGetSymbolAddress((void**)&p_xh,   g_xh);
    cudaGetSymbolAddress((void**)&p_W1h,  g_W1h);
    cudaGetSymbolAddress((void**)&p_W2h,  g_W2h);
    cudaGetSymbolAddress((void**)&p_h1,   g_h1);
    cudaGetSymbolAddress((void**)&p_hmid, g_hmid);
    cudaGetSymbolAddress((void**)&p_h2,   g_h2);
    cudaGetSymbolAddress((void**)&p_as1,  g_as1);
    cudaGetSymbolAddress((void**)&p_ad1,  g_ad1);
    cudaGetSymbolAddress((void**)&p_as2,  g_as2);
    cudaGetSymbolAddress((void**)&p_ad2,  g_ad2);
    cudaGetSymbolAddress((void**)&p_deg,  g_deg);

    // fp16 conversions (independent of CSR build)
    f2h_kernel<<<(NN * INF_C / 4 + 255) / 256, 256>>>(x, p_xh, NN * INF_C / 4);
    f2h_kernel<<<(INF_C * HEADS * HF1 / 4 + 255) / 256, 256>>>(W1, p_W1h, INF_C * HEADS * HF1 / 4);
    f2h_kernel<<<(HF1 * HEADS * OUT2 / 4 + 255) / 256, 256>>>(W2, p_W2h, HF1 * HEADS * OUT2 / 4);

    // CSR build
    cudaMemsetAsync(p_deg, 0, NN * sizeof(int));
    count_deg_kernel<<<(EE + 255) / 256, 256>>>(ei);
    scan_kernel<<<1, 1024>>>();
    fill_csr_kernel<<<(ETOT + 255) / 256, 256>>>(ei);

    // Layer 1
    {
        dim3 grid((HEADS * HF1) / 128, (NN + 127) / 128);
        h16_gemm_kernel<INF_C, HEADS * HF1><<<grid, 256>>>(NN, p_xh, p_W1h, p_h1);
    }
    attn_logits_kernel<HF1><<<NN, 4 * HF1>>>(p_h1, as1, ad1, p_as1, p_ad1);
    gat_aggregate_kernel<HF1, __half><<<NN, 4 * HF1>>>(p_h1, p_as1, p_ad1, b1, p_hmid, 1);

    // Layer 2
    {
        dim3 grid((HEADS * OUT2) / 128, (NN + 127) / 128);
        h16_gemm_kernel<HF1, HEADS * OUT2><<<grid, 256>>>(NN, p_hmid, p_W2h, p_h2);
    }
    attn_logits_kernel<OUT2><<<NN, 4 * OUT2>>>(p_h2, as2, ad2, p_as2, p_ad2);
    gat_aggregate_kernel<OUT2, float><<<NN, 4 * OUT2>>>(p_h2, p_as2, p_ad2, b2, out, 0);
}

// round 10
// speedup vs baseline: 1.1591x; 1.0580x over previous
#include <cuda_runtime.h>
#include <cuda_fp16.h>
#include <math_constants.h>

// Problem constants (fixed by the reference)
#define NN     20000
#define EE     640000
#define ETOT   (EE + NN)      // edges + self loops
#define INF_C  256
#define HEADS  8
#define HF1    64
#define OUT2   32
#define NEG_SLOPE 0.2f
#define CHUNK  128

// ---------------- static scratch (no allocations allowed) ----------------
__device__ __half g_xh  [NN * INF_C];         // x in fp16
__device__ __half g_W1h [INF_C * HEADS * HF1];
__device__ __half g_W2h [HF1 * HEADS * OUT2];
__device__ __half g_h1  [NN * HEADS * HF1];   // layer1 projected features (fp16)
__device__ __half g_hmid[NN * HF1];           // layer1 output (fp16, feeds GEMM2)
__device__ __half g_h2  [NN * HEADS * OUT2];  // layer2 projected features (fp16)
__device__ __align__(16) float g_as1 [NN * HEADS];
__device__ __align__(16) float g_ad1 [NN * HEADS];
__device__ __align__(16) float g_as2 [NN * HEADS];
__device__ __align__(16) float g_ad2 [NN * HEADS];
__device__ int   g_deg [NN];
__device__ int   g_off [NN + 1];
__device__ int   g_cur [NN];
__device__ int   g_csr [ETOT];               // src node of each edge, grouped by dst

// ---------------- prep: fp32->fp16 of x/W1/W2 + zero deg (one launch) ----------------
__device__ __forceinline__ void cvt4(const float* src, __half* dst, int i) {
    float4 v = ((const float4*)src)[i];
    ((half2*)dst)[2 * i]     = __floats2half2_rn(v.x, v.y);
    ((half2*)dst)[2 * i + 1] = __floats2half2_rn(v.z, v.w);
}

__global__ void prep_kernel(const float* __restrict__ x,
                            const float* __restrict__ W1,
                            const float* __restrict__ W2) {
    constexpr int NX  = NN * INF_C / 4;
    constexpr int NW1 = INF_C * HEADS * HF1 / 4;
    constexpr int NW2 = HF1 * HEADS * OUT2 / 4;
    int i = blockIdx.x * blockDim.x + threadIdx.x;
    if (i < NX)                        cvt4(x,  g_xh,  i);
    else if (i < NX + NW1)             cvt4(W1, g_W1h, i - NX);
    else if (i < NX + NW1 + NW2)       cvt4(W2, g_W2h, i - NX - NW1);
    else if (i < NX + NW1 + NW2 + NN)  g_deg[i - NX - NW1 - NW2] = 0;
}

// ---------------- CSR build ----------------
__global__ void count_deg_kernel(const int* __restrict__ ei) {
    int e = blockIdx.x * blockDim.x + threadIdx.x;
    if (e < EE) atomicAdd(&g_deg[ei[EE + e]], 1);
}

// exclusive scan of (deg + 1 self-loop); also initializes cursor array
__global__ void scan_kernel() {
    __shared__ int warpsum[32];
    __shared__ int carry_s;
    const int tid = threadIdx.x, lane = tid & 31, wid = tid >> 5;
    if (tid == 0) carry_s = 0;
    __syncthreads();
    for (int base = 0; base < NN; base += 1024) {
        int i = base + tid;
        int v = (i < NN) ? (g_deg[i] + 1) : 0;   // +1 = self loop
        int x = v;
        #pragma unroll
        for (int o = 1; o < 32; o <<= 1) {
            int y = __shfl_up_sync(0xFFFFFFFFu, x, o);
            if (lane >= o) x += y;
        }
        if (lane == 31) warpsum[wid] = x;
        __syncthreads();
        if (wid == 0) {
            int s = warpsum[lane];
            #pragma unroll
            for (int o = 1; o < 32; o <<= 1) {
                int y = __shfl_up_sync(0xFFFFFFFFu, s, o);
                if (lane >= o) s += y;
            }
            warpsum[lane] = s;
        }
        __syncthreads();
        int woff = wid ? warpsum[wid - 1] : 0;
        int excl = carry_s + woff + x - v;
        if (i < NN) { g_off[i] = excl; g_cur[i] = excl; }
        int total = warpsum[31];
        __syncthreads();
        if (tid == 0) carry_s += total;
        __syncthreads();
    }
    if (threadIdx.x == 0) g_off[NN] = carry_s;
}

__global__ void fill_csr_kernel(const int* __restrict__ ei) {
    int idx = blockIdx.x * blockDim.x + threadIdx.x;
    if (idx < EE) {
        int s = ei[idx];
        int d = ei[EE + idx];
        int pos = atomicAdd(&g_cur[d], 1);
        g_csr[pos] = s;
    } else if (idx < ETOT) {
        int i = idx - EE;
        int pos = atomicAdd(&g_cur[i], 1);
        g_csr[pos] = i;   // self loop
    }
}

// ---------------- fp16 GEMM + fused attention logits ----------------
// C[M,ND] = A[M,KD] @ B[KD,ND]; also computes asrc[n,h], adst[n,h] in-epilogue.
// mma.sync.m16n8k16 f16 (f32 accum). BM=128, BN=128, BK=32, 256 threads
// (8 warps, 4x2, 32x64 warp tile). CH = channels per head (64 or 32).
// Each warp tile spans whole heads -> logits reduced with quad shfls, no atomics.

__device__ __forceinline__ unsigned smaddr(const void* p) {
    return (unsigned)__cvta_generic_to_shared(p);
}

template<int KD, int ND, int CH>
__global__ __launch_bounds__(256)
void h16_gemm_kernel(int M, const __half* __restrict__ A,
                     const __half* __restrict__ B, __half* __restrict__ C,
                     const float* __restrict__ att_s, const float* __restrict__ att_d,
                     float* __restrict__ asrc, float* __restrict__ adst) {
    constexpr int BM = 128, BN = 128, BK = 32;
    constexpr int KT = KD / BK;
    __shared__ __half As[2][BM][BK + 8];   // row stride 80B (5*16B, odd) -> ldmatrix conflict-free
    __shared__ __half Bs[2][BK][BN + 8];   // row stride 272B (17*16B, odd)
    const int tid  = threadIdx.x;
    const int lane = tid & 31;
    const int warp = tid >> 5;
    const int wm = warp >> 1;              // 0..3
    const int wn = warp & 1;               // 0..1
    const int rowBase = blockIdx.y * BM;
    const int colBase = blockIdx.x * BN;

    float c[2][8][4];
    #pragma unroll
    for (int mf = 0; mf < 2; mf++)
        #pragma unroll
        for (int nf = 0; nf < 8; nf++)
            #pragma unroll
            for (int i = 0; i < 4; i++) c[mf][nf][i] = 0.f;

    const int ar = tid >> 2;               // 0..63 (+64)
    const int ac = (tid & 3) * 8;          // 0..24
    const int br = tid >> 4;               // 0..15 (+16)
    const int bc = (tid & 15) * 8;         // 0..120
    const int g  = lane >> 2;
    const int tg = lane & 3;

    uint4 aL[2], bL[2];
    const uint4 zero4 = make_uint4(0u, 0u, 0u, 0u);

    auto gload = [&](int it) {
        const int k0 = it * BK;
        #pragma unroll
        for (int i = 0; i < 2; i++) {
            int r = rowBase + ar + i * 64;
            aL[i] = (r < M) ? *(const uint4*)&A[(size_t)r * KD + k0 + ac] : zero4;
        }
        #pragma unroll
        for (int j = 0; j < 2; j++)
            bL[j] = *(const uint4*)&B[(size_t)(k0 + br + j * 16) * ND + colBase + bc];
    };
    auto sstore = [&](int buf) {
        #pragma unroll
        for (int i = 0; i < 2; i++)
            *(uint4*)&As[buf][ar + i * 64][ac] = aL[i];
        #pragma unroll
        for (int j = 0; j < 2; j++)
            *(uint4*)&Bs[buf][br + j * 16][bc] = bL[j];
    };
    auto compute = [&](int buf) {
        #pragma unroll
        for (int ks = 0; ks < 2; ks++) {
            unsigned a[2][4], b[8][2];
            #pragma unroll
            for (int mf = 0; mf < 2; mf++) {
                unsigned ad = smaddr(&As[buf][wm * 32 + mf * 16 + (lane & 15)]
                                            [ks * 16 + ((lane >> 4) & 1) * 8]);
                asm volatile(
                    "ldmatrix.sync.aligned.m8n8.x4.shared.b16 {%0,%1,%2,%3}, [%4];"
                    : "=r"(a[mf][0]), "=r"(a[mf][1]), "=r"(a[mf][2]), "=r"(a[mf][3])
                    : "r"(ad));
            }
            #pragma unroll
            for (int nq = 0; nq < 4; nq++) {
                unsigned ad = smaddr(&Bs[buf][ks * 16 + (lane & 15)]
                                            [wn * 64 + nq * 16 + ((lane >> 4) & 1) * 8]);
                asm volatile(
                    "ldmatrix.sync.aligned.m8n8.x4.trans.shared.b16 {%0,%1,%2,%3}, [%4];"
                    : "=r"(b[nq * 2][0]), "=r"(b[nq * 2][1]),
                      "=r"(b[nq * 2 + 1][0]), "=r"(b[nq * 2 + 1][1])
                    : "r"(ad));
            }
            #pragma unroll
            for (int mf = 0; mf < 2; mf++)
                #pragma unroll
                for (int nf = 0; nf < 8; nf++)
                    asm volatile(
                        "mma.sync.aligned.m16n8k16.row.col.f32.f16.f16.f32 "
                        "{%0,%1,%2,%3}, {%4,%5,%6,%7}, {%8,%9}, {%0,%1,%2,%3};"
                        : "+f"(c[mf][nf][0]), "+f"(c[mf][nf][1]),
                          "+f"(c[mf][nf][2]), "+f"(c[mf][nf][3])
                        : "r"(a[mf][0]), "r"(a[mf][1]), "r"(a[mf][2]), "r"(a[mf][3]),
                          "r"(b[nf][0]), "r"(b[nf][1]));
        }
    };

    gload(0);
    sstore(0);
    __syncthreads();
    #pragma unroll
    for (int it = 0; it < KT; it++) {
        if (it + 1 < KT) gload(it + 1);      // overlap gmem loads with compute
        compute(it & 1);
        __syncthreads();
        if (it + 1 < KT) {
            sstore((it + 1) & 1);
            __syncthreads();
        }
    }

    // ---- store C ----
    #pragma unroll
    for (int mf = 0; mf < 2; mf++) {
        #pragma unroll
        for (int nf = 0; nf < 8; nf++) {
            int col = colBase + wn * 64 + nf * 8 + tg * 2;
            int r0 = rowBase + wm * 32 + mf * 16 + g;
            if (r0 < M)
                *(half2*)&C[(size_t)r0 * ND + col] = __floats2half2_rn(c[mf][nf][0], c[mf][nf][1]);
            int r1 = r0 + 8;
            if (r1 < M)
                *(half2*)&C[(size_t)r1 * ND + col] = __floats2half2_rn(c[mf][nf][2], c[mf][nf][3]);
        }
    }

    // ---- fused attention logits ----
    // head of col (colBase + wn*64 + nf*8 + tg*2): warp tile covers NHW whole heads.
    constexpr int NFH = CH / 8;            // nf per head (8 or 4)
    constexpr int NHW = 8 / NFH;           // heads per warp tile (1 or 2)
    const int headBase = (colBase + wn * 64) / CH;
    float asv[8][2], adv[8][2];
    #pragma unroll
    for (int nf = 0; nf < 8; nf++) {
        int hl  = nf / NFH;
        int cih = (nf % NFH) * 8 + tg * 2;
        int idx = (headBase + hl) * CH + cih;
        asv[nf][0] = att_s[idx];     asv[nf][1] = att_s[idx + 1];
        adv[nf][0] = att_d[idx];     adv[nf][1] = att_d[idx + 1];
    }
    #pragma unroll
    for (int mf = 0; mf < 2; mf++) {
        float ps0[NHW], pd0[NHW], ps1[NHW], pd1[NHW];
        #pragma unroll
        for (int hl = 0; hl < NHW; hl++) { ps0[hl] = pd0[hl] = ps1[hl] = pd1[hl] = 0.f; }
        #pragma unroll
        for (int nf = 0; nf < 8; nf++) {
            int hl = nf / NFH;
            ps0[hl] += c[mf][nf][0] * asv[nf][0] + c[mf][nf][1] * asv[nf][1];
            pd0[hl] += c[mf][nf][0] * adv[nf][0] + c[mf][nf][1] * adv[nf][1];
            ps1[hl] += c[mf][nf][2] * asv[nf][0] + c[mf][nf][3] * asv[nf][1];
            pd1[hl] += c[mf][nf][2] * adv[nf][0] + c[mf][nf][3] * adv[nf][1];
        }
        int r0 = rowBase + wm * 32 + mf * 16 + g;
        int r1 = r0 + 8;
        #pragma unroll
        for (int hl = 0; hl < NHW; hl++) {
            #pragma unroll
            for (int o = 1; o <= 2; o <<= 1) {
                ps0[hl] += __shfl_xor_sync(0xFFFFFFFFu, ps0[hl], o);
                pd0[hl] += __shfl_xor_sync(0xFFFFFFFFu, pd0[hl], o);
                ps1[hl] += __shfl_xor_sync(0xFFFFFFFFu, ps1[hl], o);
                pd1[hl] += __shfl_xor_sync(0xFFFFFFFFu, pd1[hl], o);
            }
            if (tg == 0) {
                int hg = headBase + hl;
                if (r0 < M) { asrc[r0 * 8 + hg] = ps0[hl]; adst[r0 * 8 + hg] = pd0[hl]; }
                if (r1 < M) { asrc[r1 * 8 + hg] = ps1[hl]; adst[r1 * 8 + hg] = pd1[hl]; }
            }
        }
    }
}

// ---------------- GAT aggregation: single-pass unnormalized softmax ----------------
// alpha = exp(e)/sum(exp(e)) (no max-sub; |e| small). Accumulate unnormalized,
// track per-head denominator, scale at end. One block per dst node, 256 threads.
// uint2 gathers (4 channels/thread): EPB = 256/(2*CH) edges processed in parallel.
template<int CH, typename OutT>
__global__ __launch_bounds__(256)
void gat_aggregate_kernel(const __half* __restrict__ h,
                          const float* __restrict__ asrc,
                          const float* __restrict__ adst,
                          const float* __restrict__ bias,
                          OutT* __restrict__ out,
                          int do_relu) {
    constexpr int NT  = 256;
    constexpr int TPE = 2 * CH;            // threads per edge (128 or 64)
    constexpr int EPB = NT / TPE;          // edges in parallel (2 or 4)
    const int d = blockIdx.x;
    const int t = threadIdx.x;
    const int start = g_off[d];
    const int deg = g_off[d + 1] - start;

    __shared__ float sm_adst[8], sm_is[8];
    __shared__ int   s_src[CHUNK];
    __shared__ float s_w[CHUNK * 8];
    __shared__ float s_dp[NT];
    __shared__ float s_red[EPB][8][CH];

    if (t < 8) sm_adst[t] = adst[d * 8 + t];
    __syncthreads();

    const int sub = t / TPE;               // which edge of the group
    const int rr  = t % TPE;
    const int hh  = rr / (CH / 4);         // head
    const int cq  = rr % (CH / 4);         // channel quad (4 channels)
    const uint2* __restrict__ h4p = (const uint2*)h;
    float4 acc = make_float4(0.f, 0.f, 0.f, 0.f);
    float denp = 0.f;

    for (int base = 0; base < deg; base += CHUNK) {
        const int cnt = min(CHUNK, deg - base);
        if (t < cnt) s_src[t] = g_csr[start + base + t];
        __syncthreads();
        // weights: entry idx -> edge idx>>3, head idx&7
        for (int idx = t; idx < cnt * 8; idx += NT) {
            int j = idx >> 3, h2 = idx & 7;
            int s = s_src[j];
            float e = asrc[s * 8 + h2] + sm_adst[h2];
            e = (e > 0.f) ? e : NEG_SLOPE * e;
            float w = __expf(e);
            s_w[idx] = w;
            denp += w;
        }
        __syncthreads();
        #pragma unroll 8
        for (int j = sub; j < cnt; j += EPB) {
            float w = s_w[j * 8 + hh];
            uint2 raw = h4p[(size_t)s_src[j] * (2 * CH) + hh * (CH / 4) + cq];
            float2 v0 = __half22float2(*(const half2*)&raw.x);
            float2 v1 = __half22float2(*(const half2*)&raw.y);
            acc.x = fmaf(w, v0.x, acc.x);
            acc.y = fmaf(w, v0.y, acc.y);
            acc.z = fmaf(w, v1.x, acc.z);
            acc.w = fmaf(w, v1.y, acc.w);
        }
        __syncthreads();
    }

    // reduce per-head denominators (thread t contributed to head t&7)
    s_dp[t] = denp;
    __syncthreads();
    if (t < 8) {
        float tot = 0.f;
        #pragma unroll
        for (int k = t; k < NT; k += 8) tot += s_dp[k];
        sm_is[t] = 1.0f / tot;
    }
    __syncthreads();

    const float is = sm_is[hh];
    *(float4*)&s_red[sub][hh][cq * 4] = make_float4(acc.x * is, acc.y * is,
                                                    acc.z * is, acc.w * is);
    __syncthreads();
    if (t < CH) {
        float v = 0.f;
        #pragma unroll
        for (int sb = 0; sb < EPB; sb++)
            #pragma unroll
            for (int k = 0; k < 8; k++) v += s_red[sb][k][t];
        v = v * 0.125f + bias[t];
        if (do_relu) v = fmaxf(v, 0.f);
        if constexpr (sizeof(OutT) == 2)
            out[(size_t)d * CH + t] = __float2half(v);
        else
            out[(size_t)d * CH + t] = v;
    }
}

// ---------------- launch ----------------
extern "C" void kernel_launch(void* const* d_in, const int* in_sizes, int n_in,
                              void* d_out, int out_size) {
    const float* x    = (const float*)d_in[0];
    const int*   ei   = (const int*)  d_in[1];
    const float* W1   = (const float*)d_in[2];
    const float* as1  = (const float*)d_in[3];
    const float* ad1  = (const float*)d_in[4];
    const float* b1   = (const float*)d_in[5];
    const float* W2   = (const float*)d_in[6];
    const float* as2  = (const float*)d_in[7];
    const float* ad2  = (const float*)d_in[8];
    const float* b2   = (const float*)d_in[9];
    float* out = (float*)d_out;

    __half *p_xh, *p_W1h, *p_W2h, *p_h1, *p_hmid, *p_h2;
    float *p_as1, *p_ad1, *p_as2, *p_ad2;
    cudaGetSymbolAddress((void**)&p_xh,   g_xh);
    cudaGetSymbolAddress((void**)&p_W1h,  g_W1h);
    cudaGetSymbolAddress((void**)&p_W2h,  g_W2h);
    cudaGetSymbolAddress((void**)&p_h1,   g_h1);
    cudaGetSymbolAddress((void**)&p_hmid, g_hmid);
    cudaGetSymbolAddress((void**)&p_h2,   g_h2);
    cudaGetSymbolAddress((void**)&p_as1,  g_as1);
    cudaGetSymbolAddress((void**)&p_ad1,  g_ad1);
    cudaGetSymbolAddress((void**)&p_as2,  g_as2);
    cudaGetSymbolAddress((void**)&p_ad2,  g_ad2);

    // 1: prep (f2h x/W1/W2 + zero deg)
    constexpr int PREP_ITEMS = NN * INF_C / 4 + INF_C * HEADS * HF1 / 4
                             + HF1 * HEADS * OUT2 / 4 + NN;
    prep_kernel<<<(PREP_ITEMS + 255) / 256, 256>>>(x, W1, W2);
    // 2-4: CSR build
    count_deg_kernel<<<(EE + 255) / 256, 256>>>(ei);
    scan_kernel<<<1, 1024>>>();
    fill_csr_kernel<<<(ETOT + 255) / 256, 256>>>(ei);

    // 5: GEMM1 + logits1
    {
        dim3 grid((HEADS * HF1) / 128, (NN + 127) / 128);
        h16_gemm_kernel<INF_C, HEADS * HF1, HF1><<<grid, 256>>>(
            NN, p_xh, p_W1h, p_h1, as1, ad1, p_as1, p_ad1);
    }
    // 6: aggregation 1  (ncu -s 5 -c 1 lands here)
    gat_aggregate_kernel<HF1, __half><<<NN, 256>>>(p_h1, p_as1, p_ad1, b1, p_hmid, 1);

    // 7: GEMM2 + logits2
    {
        dim3 grid((HEADS * OUT2) / 128, (NN + 127) / 128);
        h16_gemm_kernel<HF1, HEADS * OUT2, OUT2><<<grid, 256>>>(
            NN, p_hmid, p_W2h, p_h2, as2, ad2, p_as2, p_ad2);
    }
    // 8: aggregation 2
    gat_aggregate_kernel<OUT2, float><<<NN, 256>>>(p_h2, p_as2, p_ad2, b2, out, 0);
}

// round 11
// speedup vs baseline: 1.1808x; 1.0187x over previous
#include <cuda_runtime.h>
#include <cuda_fp16.h>
#include <math_constants.h>

// Problem constants (fixed by the reference)
#define NN     20000
#define EE     640000
#define ETOT   (EE + NN)      // edges + self loops
#define INF_C  256
#define HEADS  8
#define HF1    64
#define OUT2   32
#define NEG_SLOPE 0.2f

// ---------------- static scratch (no allocations allowed) ----------------
__device__ __half g_xh  [NN * INF_C];         // x in fp16
__device__ __half g_W1h [INF_C * HEADS * HF1];
__device__ __half g_W2h [HF1 * HEADS * OUT2];
__device__ __half g_h1  [NN * HEADS * HF1];   // layer1 projected features (fp16)
__device__ __half g_hmid[NN * HF1];           // layer1 output (fp16, feeds GEMM2)
__device__ __half g_h2  [NN * HEADS * OUT2];  // layer2 projected features (fp16)
__device__ __align__(16) float g_as1 [NN * HEADS];
__device__ __align__(16) float g_ad1 [NN * HEADS];
__device__ __align__(16) float g_as2 [NN * HEADS];
__device__ __align__(16) float g_ad2 [NN * HEADS];
__device__ int   g_deg [NN];
__device__ int   g_off [NN + 1];
__device__ int   g_cur [NN];
__device__ int   g_csr [ETOT];               // src node of each edge, grouped by dst

// ---------------- prep: fp32->fp16 of x/W1/W2 + degree count (one launch) --------
// g_deg zeroed by cudaMemsetAsync before this kernel (stream-ordered).
__device__ __forceinline__ void cvt4(const float* src, __half* dst, int i) {
    float4 v = ((const float4*)src)[i];
    ((half2*)dst)[2 * i]     = __floats2half2_rn(v.x, v.y);
    ((half2*)dst)[2 * i + 1] = __floats2half2_rn(v.z, v.w);
}

__global__ void prep_kernel(const float* __restrict__ x,
                            const float* __restrict__ W1,
                            const float* __restrict__ W2,
                            const int* __restrict__ ei) {
    constexpr int NX  = NN * INF_C / 4;
    constexpr int NW1 = INF_C * HEADS * HF1 / 4;
    constexpr int NW2 = HF1 * HEADS * OUT2 / 4;
    int i = blockIdx.x * blockDim.x + threadIdx.x;
    if (i < NX)                        cvt4(x,  g_xh,  i);
    else if (i < NX + NW1)             cvt4(W1, g_W1h, i - NX);
    else if (i < NX + NW1 + NW2)       cvt4(W2, g_W2h, i - NX - NW1);
    else if (i < NX + NW1 + NW2 + EE)  atomicAdd(&g_deg[ei[EE + (i - NX - NW1 - NW2)]], 1);
}

// ---------------- CSR build ----------------
// exclusive scan of (deg + 1 self-loop); also initializes cursor array
__global__ void scan_kernel() {
    __shared__ int warpsum[32];
    __shared__ int carry_s;
    const int tid = threadIdx.x, lane = tid & 31, wid = tid >> 5;
    if (tid == 0) carry_s = 0;
    __syncthreads();
    for (int base = 0; base < NN; base += 1024) {
        int i = base + tid;
        int v = (i < NN) ? (g_deg[i] + 1) : 0;   // +1 = self loop
        int x = v;
        #pragma unroll
        for (int o = 1; o < 32; o <<= 1) {
            int y = __shfl_up_sync(0xFFFFFFFFu, x, o);
            if (lane >= o) x += y;
        }
        if (lane == 31) warpsum[wid] = x;
        __syncthreads();
        if (wid == 0) {
            int s = warpsum[lane];
            #pragma unroll
            for (int o = 1; o < 32; o <<= 1) {
                int y = __shfl_up_sync(0xFFFFFFFFu, s, o);
                if (lane >= o) s += y;
            }
            warpsum[lane] = s;
        }
        __syncthreads();
        int woff = wid ? warpsum[wid - 1] : 0;
        int excl = carry_s + woff + x - v;
        if (i < NN) { g_off[i] = excl; g_cur[i] = excl; }
        int total = warpsum[31];
        __syncthreads();
        if (tid == 0) carry_s += total;
        __syncthreads();
    }
    if (threadIdx.x == 0) g_off[NN] = carry_s;
}

__global__ void fill_csr_kernel(const int* __restrict__ ei) {
    int idx = blockIdx.x * blockDim.x + threadIdx.x;
    if (idx < EE) {
        int s = ei[idx];
        int d = ei[EE + idx];
        int pos = atomicAdd(&g_cur[d], 1);
        g_csr[pos] = s;
    } else if (idx < ETOT) {
        int i = idx - EE;
        int pos = atomicAdd(&g_cur[i], 1);
        g_csr[pos] = i;   // self loop
    }
}

// ---------------- fp16 GEMM + fused attention logits ----------------
// C[M,ND] = A[M,KD] @ B[KD,ND]; also computes asrc[n,h], adst[n,h] in-epilogue.
// mma.sync.m16n8k16 f16 (f32 accum). BM=128, BN=128, BK=32, 256 threads
// (8 warps, 4x2, 32x64 warp tile). CH = channels per head (64 or 32).

__device__ __forceinline__ unsigned smaddr(const void* p) {
    return (unsigned)__cvta_generic_to_shared(p);
}

template<int KD, int ND, int CH>
__global__ __launch_bounds__(256)
void h16_gemm_kernel(int M, const __half* __restrict__ A,
                     const __half* __restrict__ B, __half* __restrict__ C,
                     const float* __restrict__ att_s, const float* __restrict__ att_d,
                     float* __restrict__ asrc, float* __restrict__ adst) {
    constexpr int BM = 128, BN = 128, BK = 32;
    constexpr int KT = KD / BK;
    __shared__ __half As[2][BM][BK + 8];   // row stride 80B (5*16B, odd) -> ldmatrix conflict-free
    __shared__ __half Bs[2][BK][BN + 8];   // row stride 272B (17*16B, odd)
    const int tid  = threadIdx.x;
    const int lane = tid & 31;
    const int warp = tid >> 5;
    const int wm = warp >> 1;              // 0..3
    const int wn = warp & 1;               // 0..1
    const int rowBase = blockIdx.y * BM;
    const int colBase = blockIdx.x * BN;

    float c[2][8][4];
    #pragma unroll
    for (int mf = 0; mf < 2; mf++)
        #pragma unroll
        for (int nf = 0; nf < 8; nf++)
            #pragma unroll
            for (int i = 0; i < 4; i++) c[mf][nf][i] = 0.f;

    const int ar = tid >> 2;               // 0..63 (+64)
    const int ac = (tid & 3) * 8;          // 0..24
    const int br = tid >> 4;               // 0..15 (+16)
    const int bc = (tid & 15) * 8;         // 0..120
    const int g  = lane >> 2;
    const int tg = lane & 3;

    uint4 aL[2], bL[2];
    const uint4 zero4 = make_uint4(0u, 0u, 0u, 0u);

    auto gload = [&](int it) {
        const int k0 = it * BK;
        #pragma unroll
        for (int i = 0; i < 2; i++) {
            int r = rowBase + ar + i * 64;
            aL[i] = (r < M) ? *(const uint4*)&A[(size_t)r * KD + k0 + ac] : zero4;
        }
        #pragma unroll
        for (int j = 0; j < 2; j++)
            bL[j] = *(const uint4*)&B[(size_t)(k0 + br + j * 16) * ND + colBase + bc];
    };
    auto sstore = [&](int buf) {
        #pragma unroll
        for (int i = 0; i < 2; i++)
            *(uint4*)&As[buf][ar + i * 64][ac] = aL[i];
        #pragma unroll
        for (int j = 0; j < 2; j++)
            *(uint4*)&Bs[buf][br + j * 16][bc] = bL[j];
    };
    auto compute = [&](int buf) {
        #pragma unroll
        for (int ks = 0; ks < 2; ks++) {
            unsigned a[2][4], b[8][2];
            #pragma unroll
            for (int mf = 0; mf < 2; mf++) {
                unsigned ad = smaddr(&As[buf][wm * 32 + mf * 16 + (lane & 15)]
                                            [ks * 16 + ((lane >> 4) & 1) * 8]);
                asm volatile(
                    "ldmatrix.sync.aligned.m8n8.x4.shared.b16 {%0,%1,%2,%3}, [%4];"
                    : "=r"(a[mf][0]), "=r"(a[mf][1]), "=r"(a[mf][2]), "=r"(a[mf][3])
                    : "r"(ad));
            }
            #pragma unroll
            for (int nq = 0; nq < 4; nq++) {
                unsigned ad = smaddr(&Bs[buf][ks * 16 + (lane & 15)]
                                            [wn * 64 + nq * 16 + ((lane >> 4) & 1) * 8]);
                asm volatile(
                    "ldmatrix.sync.aligned.m8n8.x4.trans.shared.b16 {%0,%1,%2,%3}, [%4];"
                    : "=r"(b[nq * 2][0]), "=r"(b[nq * 2][1]),
                      "=r"(b[nq * 2 + 1][0]), "=r"(b[nq * 2 + 1][1])
                    : "r"(ad));
            }
            #pragma unroll
            for (int mf = 0; mf < 2; mf++)
                #pragma unroll
                for (int nf = 0; nf < 8; nf++)
                    asm volatile(
                        "mma.sync.aligned.m16n8k16.row.col.f32.f16.f16.f32 "
                        "{%0,%1,%2,%3}, {%4,%5,%6,%7}, {%8,%9}, {%0,%1,%2,%3};"
                        : "+f"(c[mf][nf][0]), "+f"(c[mf][nf][1]),
                          "+f"(c[mf][nf][2]), "+f"(c[mf][nf][3])
                        : "r"(a[mf][0]), "r"(a[mf][1]), "r"(a[mf][2]), "r"(a[mf][3]),
                          "r"(b[nf][0]), "r"(b[nf][1]));
        }
    };

    gload(0);
    sstore(0);
    __syncthreads();
    #pragma unroll
    for (int it = 0; it < KT; it++) {
        if (it + 1 < KT) gload(it + 1);      // overlap gmem loads with compute
        compute(it & 1);
        __syncthreads();
        if (it + 1 < KT) {
            sstore((it + 1) & 1);
            __syncthreads();
        }
    }

    // ---- store C ----
    #pragma unroll
    for (int mf = 0; mf < 2; mf++) {
        #pragma unroll
        for (int nf = 0; nf < 8; nf++) {
            int col = colBase + wn * 64 + nf * 8 + tg * 2;
            int r0 = rowBase + wm * 32 + mf * 16 + g;
            if (r0 < M)
                *(half2*)&C[(size_t)r0 * ND + col] = __floats2half2_rn(c[mf][nf][0], c[mf][nf][1]);
            int r1 = r0 + 8;
            if (r1 < M)
                *(half2*)&C[(size_t)r1 * ND + col] = __floats2half2_rn(c[mf][nf][2], c[mf][nf][3]);
        }
    }

    // ---- fused attention logits ----
    constexpr int NFH = CH / 8;            // nf per head (8 or 4)
    constexpr int NHW = 8 / NFH;           // heads per warp tile (1 or 2)
    const int headBase = (colBase + wn * 64) / CH;
    float asv[8][2], adv[8][2];
    #pragma unroll
    for (int nf = 0; nf < 8; nf++) {
        int hl  = nf / NFH;
        int cih = (nf % NFH) * 8 + tg * 2;
        int idx = (headBase + hl) * CH + cih;
        asv[nf][0] = att_s[idx];     asv[nf][1] = att_s[idx + 1];
        adv[nf][0] = att_d[idx];     adv[nf][1] = att_d[idx + 1];
    }
    #pragma unroll
    for (int mf = 0; mf < 2; mf++) {
        float ps0[NHW], pd0[NHW], ps1[NHW], pd1[NHW];
        #pragma unroll
        for (int hl = 0; hl < NHW; hl++) { ps0[hl] = pd0[hl] = ps1[hl] = pd1[hl] = 0.f; }
        #pragma unroll
        for (int nf = 0; nf < 8; nf++) {
            int hl = nf / NFH;
            ps0[hl] += c[mf][nf][0] * asv[nf][0] + c[mf][nf][1] * asv[nf][1];
            pd0[hl] += c[mf][nf][0] * adv[nf][0] + c[mf][nf][1] * adv[nf][1];
            ps1[hl] += c[mf][nf][2] * asv[nf][0] + c[mf][nf][3] * asv[nf][1];
            pd1[hl] += c[mf][nf][2] * adv[nf][0] + c[mf][nf][3] * adv[nf][1];
        }
        int r0 = rowBase + wm * 32 + mf * 16 + g;
        int r1 = r0 + 8;
        #pragma unroll
        for (int hl = 0; hl < NHW; hl++) {
            #pragma unroll
            for (int o = 1; o <= 2; o <<= 1) {
                ps0[hl] += __shfl_xor_sync(0xFFFFFFFFu, ps0[hl], o);
                pd0[hl] += __shfl_xor_sync(0xFFFFFFFFu, pd0[hl], o);
                ps1[hl] += __shfl_xor_sync(0xFFFFFFFFu, ps1[hl], o);
                pd1[hl] += __shfl_xor_sync(0xFFFFFFFFu, pd1[hl], o);
            }
            if (tg == 0) {
                int hg = headBase + hl;
                if (r0 < M) { asrc[r0 * 8 + hg] = ps0[hl]; adst[r0 * 8 + hg] = pd0[hl]; }
                if (r1 < M) { asrc[r1 * 8 + hg] = ps1[hl]; adst[r1 * 8 + hg] = pd1[hl]; }
            }
        }
    }
}

// ---------------- GAT aggregation: single-pass unnormalized softmax ----------------
// alpha = exp(e)/sum(exp(e)) (no max-sub; |e| small). Accumulate unnormalized,
// track per-head denominator, scale at end. One block per dst node, 256 threads.
// uint4 gathers (8 channels/thread): TPE = CH threads/edge, EPB = 256/CH edges
// in flight per inner step.
template<int CH, typename OutT>
__global__ __launch_bounds__(256)
void gat_aggregate_kernel(const __half* __restrict__ h,
                          const float* __restrict__ asrc,
                          const float* __restrict__ adst,
                          const float* __restrict__ bias,
                          OutT* __restrict__ out,
                          int do_relu) {
    constexpr int NT   = 256;
    constexpr int CK   = 256;              // chunk size
    constexpr int TPE  = CH;               // threads per edge (row = CH uint4)
    constexpr int EPB  = NT / TPE;         // edges in parallel (4 or 8)
    constexpr int TPH  = CH / 8;           // threads per head (8 or 4)
    const int d = blockIdx.x;
    const int t = threadIdx.x;
    const int start = g_off[d];
    const int deg = g_off[d + 1] - start;

    __shared__ float sm_adst[8], sm_is[8];
    __shared__ int   s_src[CK];
    __shared__ float s_w[CK * 8];
    __shared__ float s_dp[NT];
    __shared__ float s_red[EPB][8][CH];

    if (t < 8) sm_adst[t] = adst[d * 8 + t];
    __syncthreads();

    const int sub = t / TPE;               // which edge of the group
    const int rr  = t % TPE;
    const int hh  = rr / TPH;              // head
    const int co  = rr % TPH;              // uint4 index within head (8 channels)
    const uint4* __restrict__ h8p = (const uint4*)h;
    float acc[8] = {0.f, 0.f, 0.f, 0.f, 0.f, 0.f, 0.f, 0.f};
    float denp = 0.f;

    for (int base = 0; base < deg; base += CK) {
        const int cnt = min(CK, deg - base);
        if (t < cnt) s_src[t] = g_csr[start + base + t];
        __syncthreads();
        // weights: entry idx -> edge idx>>3, head idx&7
        for (int idx = t; idx < cnt * 8; idx += NT) {
            int j = idx >> 3, h2 = idx & 7;
            int s = s_src[j];
            float e = asrc[s * 8 + h2] + sm_adst[h2];
            e = (e > 0.f) ? e : NEG_SLOPE * e;
            float w = __expf(e);
            s_w[idx] = w;
            denp += w;
        }
        __syncthreads();
        #pragma unroll 4
        for (int j = sub; j < cnt; j += EPB) {
            float w = s_w[j * 8 + hh];
            uint4 raw = h8p[(size_t)s_src[j] * CH + hh * TPH + co];
            float2 v0 = __half22float2(*(const half2*)&raw.x);
            float2 v1 = __half22float2(*(const half2*)&raw.y);
            float2 v2 = __half22float2(*(const half2*)&raw.z);
            float2 v3 = __half22float2(*(const half2*)&raw.w);
            acc[0] = fmaf(w, v0.x, acc[0]);
            acc[1] = fmaf(w, v0.y, acc[1]);
            acc[2] = fmaf(w, v1.x, acc[2]);
            acc[3] = fmaf(w, v1.y, acc[3]);
            acc[4] = fmaf(w, v2.x, acc[4]);
            acc[5] = fmaf(w, v2.y, acc[5]);
            acc[6] = fmaf(w, v3.x, acc[6]);
            acc[7] = fmaf(w, v3.y, acc[7]);
        }
        __syncthreads();
    }

    // reduce per-head denominators (thread t contributed to head t&7)
    s_dp[t] = denp;
    __syncthreads();
    if (t < 8) {
        float tot = 0.f;
        #pragma unroll
        for (int k = t; k < NT; k += 8) tot += s_dp[k];
        sm_is[t] = 1.0f / tot;
    }
    __syncthreads();

    const float is = sm_is[hh];
    *(float4*)&s_red[sub][hh][co * 8]     = make_float4(acc[0] * is, acc[1] * is,
                                                        acc[2] * is, acc[3] * is);
    *(float4*)&s_red[sub][hh][co * 8 + 4] = make_float4(acc[4] * is, acc[5] * is,
                                                        acc[6] * is, acc[7] * is);
    __syncthreads();
    if (t < CH) {
        float v = 0.f;
        #pragma unroll
        for (int sb = 0; sb < EPB; sb++)
            #pragma unroll
            for (int k = 0; k < 8; k++) v += s_red[sb][k][t];
        v = v * 0.125f + bias[t];
        if (do_relu) v = fmaxf(v, 0.f);
        if constexpr (sizeof(OutT) == 2)
            out[(size_t)d * CH + t] = __float2half(v);
        else
            out[(size_t)d * CH + t] = v;
    }
}

// ---------------- launch ----------------
extern "C" void kernel_launch(void* const* d_in, const int* in_sizes, int n_in,
                              void* d_out, int out_size) {
    const float* x    = (const float*)d_in[0];
    const int*   ei   = (const int*)  d_in[1];
    const float* W1   = (const float*)d_in[2];
    const float* as1  = (const float*)d_in[3];
    const float* ad1  = (const float*)d_in[4];
    const float* b1   = (const float*)d_in[5];
    const float* W2   = (const float*)d_in[6];
    const float* as2  = (const float*)d_in[7];
    const float* ad2  = (const float*)d_in[8];
    const float* b2   = (const float*)d_in[9];
    float* out = (float*)d_out;

    __half *p_xh, *p_W1h, *p_W2h, *p_h1, *p_hmid, *p_h2;
    float *p_as1, *p_ad1, *p_as2, *p_ad2;
    int *p_deg;
    cudaGetSymbolAddress((void**)&p_xh,   g_xh);
    cudaGetSymbolAddress((void**)&p_W1h,  g_W1h);
    cudaGetSymbolAddress((void**)&p_W2h,  g_W2h);
    cudaGetSymbolAddress((void**)&p_h1,   g_h1);
    cudaGetSymbolAddress((void**)&p_hmid, g_hmid);
    cudaGetSymbolAddress((void**)&p_h2,   g_h2);
    cudaGetSymbolAddress((void**)&p_as1,  g_as1);
    cudaGetSymbolAddress((void**)&p_ad1,  g_ad1);
    cudaGetSymbolAddress((void**)&p_as2,  g_as2);
    cudaGetSymbolAddress((void**)&p_ad2,  g_ad2);
    cudaGetSymbolAddress((void**)&p_deg,  g_deg);

    // CSR + fp16 prep
    cudaMemsetAsync(p_deg, 0, NN * sizeof(int));
    constexpr int PREP_ITEMS = NN * INF_C / 4 + INF_C * HEADS * HF1 / 4
                             + HF1 * HEADS * OUT2 / 4 + EE;
    prep_kernel<<<(PREP_ITEMS + 255) / 256, 256>>>(x, W1, W2, ei);
    scan_kernel<<<1, 1024>>>();
    fill_csr_kernel<<<(ETOT + 255) / 256, 256>>>(ei);

    // GEMM1 + logits1
    {
        dim3 grid((HEADS * HF1) / 128, (NN + 127) / 128);
        h16_gemm_kernel<INF_C, HEADS * HF1, HF1><<<grid, 256>>>(
            NN, p_xh, p_W1h, p_h1, as1, ad1, p_as1, p_ad1);
    }
    // aggregation 1
    gat_aggregate_kernel<HF1, __half><<<NN, 256>>>(p_h1, p_as1, p_ad1, b1, p_hmid, 1);

    // GEMM2 + logits2
    {
        dim3 grid((HEADS * OUT2) / 128, (NN + 127) / 128);
        h16_gemm_kernel<HF1, HEADS * OUT2, OUT2><<<grid, 256>>>(
            NN, p_hmid, p_W2h, p_h2, as2, ad2, p_as2, p_ad2);
    }
    // aggregation 2
    gat_aggregate_kernel<OUT2, float><<<NN, 256>>>(p_h2, p_as2, p_ad2, b2, out, 0);
}

// round 13
// speedup vs baseline: 1.2049x; 1.0205x over previous
#include <cuda_runtime.h>
#include <cuda_fp16.h>
#include <math_constants.h>

// Problem constants (fixed by the reference)
#define NN     20000
#define EE     640000
#define ETOT   (EE + NN)      // edges + self loops
#define INF_C  256
#define HEADS  8
#define HF1    64
#define OUT2   32
#define NEG_SLOPE 0.2f

// ---------------- static scratch (no allocations allowed) ----------------
__device__ __half g_xh  [NN * INF_C];         // x in fp16
__device__ __half g_W1h [INF_C * HEADS * HF1];
__device__ __half g_W2h [HF1 * HEADS * OUT2];
__device__ __half g_h1  [NN * HEADS * HF1];   // layer1 projected features (fp16)
__device__ __half g_hmid[NN * HF1];           // layer1 output (fp16, feeds GEMM2)
__device__ __half g_h2  [NN * HEADS * OUT2];  // layer2 projected features (fp16)
__device__ __align__(16) float g_as1 [NN * HEADS];
__device__ __align__(16) float g_ad1 [NN * HEADS];
__device__ __align__(16) float g_as2 [NN * HEADS];
__device__ __align__(16) float g_ad2 [NN * HEADS];
__device__ int   g_deg [NN];
__device__ int   g_off [NN + 1];
__device__ int   g_cur [NN];
__device__ int   g_csr [ETOT];               // src node of each edge, grouped by dst

// ---------------- prep: fp32->fp16 of x/W1/W2 + degree count (one launch) --------
// g_deg zeroed by cudaMemsetAsync before this kernel (stream-ordered).
__device__ __forceinline__ void cvt4(const float* src, __half* dst, int i) {
    float4 v = ((const float4*)src)[i];
    ((half2*)dst)[2 * i]     = __floats2half2_rn(v.x, v.y);
    ((half2*)dst)[2 * i + 1] = __floats2half2_rn(v.z, v.w);
}

__global__ void prep_kernel(const float* __restrict__ x,
                            const float* __restrict__ W1,
                            const float* __restrict__ W2,
                            const int* __restrict__ ei) {
    constexpr int NX  = NN * INF_C / 4;
    constexpr int NW1 = INF_C * HEADS * HF1 / 4;
    constexpr int NW2 = HF1 * HEADS * OUT2 / 4;
    int i = blockIdx.x * blockDim.x + threadIdx.x;
    if (i < NX)                        cvt4(x,  g_xh,  i);
    else if (i < NX + NW1)             cvt4(W1, g_W1h, i - NX);
    else if (i < NX + NW1 + NW2)       cvt4(W2, g_W2h, i - NX - NW1);
    else if (i < NX + NW1 + NW2 + EE)  atomicAdd(&g_deg[ei[EE + (i - NX - NW1 - NW2)]], 1);
}

// ---------------- CSR build ----------------
// exclusive scan of (deg + 1 self-loop); also initializes cursor array
__global__ void scan_kernel() {
    __shared__ int warpsum[32];
    __shared__ int carry_s;
    const int tid = threadIdx.x, lane = tid & 31, wid = tid >> 5;
    if (tid == 0) carry_s = 0;
    __syncthreads();
    for (int base = 0; base < NN; base += 1024) {
        int i = base + tid;
        int v = (i < NN) ? (g_deg[i] + 1) : 0;   // +1 = self loop
        int x = v;
        #pragma unroll
        for (int o = 1; o < 32; o <<= 1) {
            int y = __shfl_up_sync(0xFFFFFFFFu, x, o);
            if (lane >= o) x += y;
        }
        if (lane == 31) warpsum[wid] = x;
        __syncthreads();
        if (wid == 0) {
            int s = warpsum[lane];
            #pragma unroll
            for (int o = 1; o < 32; o <<= 1) {
                int y = __shfl_up_sync(0xFFFFFFFFu, s, o);
                if (lane >= o) s += y;
            }
            warpsum[lane] = s;
        }
        __syncthreads();
        int woff = wid ? warpsum[wid - 1] : 0;
        int excl = carry_s + woff + x - v;
        if (i < NN) { g_off[i] = excl; g_cur[i] = excl; }
        int total = warpsum[31];
        __syncthreads();
        if (tid == 0) carry_s += total;
        __syncthreads();
    }
    if (threadIdx.x == 0) g_off[NN] = carry_s;
}

__global__ void fill_csr_kernel(const int* __restrict__ ei) {
    int idx = blockIdx.x * blockDim.x + threadIdx.x;
    if (idx < EE) {
        int s = ei[idx];
        int d = ei[EE + idx];
        int pos = atomicAdd(&g_cur[d], 1);
        g_csr[pos] = s;
    } else if (idx < ETOT) {
        int i = idx - EE;
        int pos = atomicAdd(&g_cur[i], 1);
        g_csr[pos] = i;   // self loop
    }
}

// ---------------- fp16 GEMM (cp.async pipeline) + fused attention logits ----------
// C[M,ND] = A[M,KD] @ B[KD,ND]; also computes asrc[n,h], adst[n,h] in-epilogue.
// mma.sync.m16n8k16 f16 (f32 accum). BM=128, BN=128, BK=32, 256 threads
// (8 warps, 4x2, 32x64 warp tile). ST-stage cp.async pipeline, one sync/iter.

__device__ __forceinline__ unsigned smaddr(const void* p) {
    return (unsigned)__cvta_generic_to_shared(p);
}

__device__ __forceinline__ void cp_async16(unsigned dst, const void* src, bool valid) {
    int sz = valid ? 16 : 0;   // src-size 0 -> zero-fill 16B
    asm volatile("cp.async.cg.shared.global [%0], [%1], 16, %2;"
                 :: "r"(dst), "l"(src), "r"(sz));
}

template<int KD, int ND, int CH>
__global__ __launch_bounds__(256)
void h16_gemm_kernel(int M, const __half* __restrict__ A,
                     const __half* __restrict__ B, __half* __restrict__ C,
                     const float* __restrict__ att_s, const float* __restrict__ att_d,
                     float* __restrict__ asrc, float* __restrict__ adst) {
    constexpr int BM = 128, BN = 128, BK = 32;
    constexpr int KT = KD / BK;
    constexpr int ST = (KT >= 3) ? 3 : 2;          // pipeline stages
    constexpr int AS_STRIDE = BK + 8;              // 80B rows (odd*16B): ldmatrix conflict-free
    constexpr int BS_STRIDE = BN + 8;              // 272B rows (odd*16B)

    extern __shared__ __align__(16) char smem_raw[];
    typedef __half (*AsPtr)[BM][AS_STRIDE];
    typedef __half (*BsPtr)[BK][BS_STRIDE];
    AsPtr As = reinterpret_cast<AsPtr>(smem_raw);
    BsPtr Bs = reinterpret_cast<BsPtr>(smem_raw + (size_t)ST * BM * AS_STRIDE * sizeof(__half));

    const int tid  = threadIdx.x;
    const int lane = tid & 31;
    const int warp = tid >> 5;
    const int wm = warp >> 1;              // 0..3
    const int wn = warp & 1;               // 0..1
    const int rowBase = blockIdx.y * BM;
    const int colBase = blockIdx.x * BN;

    float c[2][8][4];
    #pragma unroll
    for (int mf = 0; mf < 2; mf++)
        #pragma unroll
        for (int nf = 0; nf < 8; nf++)
            #pragma unroll
            for (int i = 0; i < 4; i++) c[mf][nf][i] = 0.f;

    const int ar = tid >> 2;               // 0..63 (+64)
    const int ac = (tid & 3) * 8;          // 0..24
    const int br = tid >> 4;               // 0..15 (+16)
    const int bc = (tid & 15) * 8;         // 0..120
    const int g  = lane >> 2;
    const int tg = lane & 3;

    auto issue = [&](int it) {             // stage `it` -> buffer it%ST; 1 commit group
        const int buf = it % ST;
        const int k0 = it * BK;
        #pragma unroll
        for (int i = 0; i < 2; i++) {
            int r = rowBase + ar + i * 64;
            cp_async16(smaddr(&As[buf][ar + i * 64][ac]),
                       &A[(size_t)r * KD + k0 + ac], r < M);
        }
        #pragma unroll
        for (int j = 0; j < 2; j++)
            cp_async16(smaddr(&Bs[buf][br + j * 16][bc]),
                       &B[(size_t)(k0 + br + j * 16) * ND + colBase + bc], true);
        asm volatile("cp.async.commit_group;");
    };

    auto compute = [&](int buf) {
        #pragma unroll
        for (int ks = 0; ks < 2; ks++) {
            unsigned a[2][4], b[8][2];
            #pragma unroll
            for (int mf = 0; mf < 2; mf++) {
                unsigned ad = smaddr(&As[buf][wm * 32 + mf * 16 + (lane & 15)]
                                            [ks * 16 + ((lane >> 4) & 1) * 8]);
                asm volatile(
                    "ldmatrix.sync.aligned.m8n8.x4.shared.b16 {%0,%1,%2,%3}, [%4];"
                    : "=r"(a[mf][0]), "=r"(a[mf][1]), "=r"(a[mf][2]), "=r"(a[mf][3])
                    : "r"(ad));
            }
            #pragma unroll
            for (int nq = 0; nq < 4; nq++) {
                unsigned ad = smaddr(&Bs[buf][ks * 16 + (lane & 15)]
                                            [wn * 64 + nq * 16 + ((lane >> 4) & 1) * 8]);
                asm volatile(
                    "ldmatrix.sync.aligned.m8n8.x4.trans.shared.b16 {%0,%1,%2,%3}, [%4];"
                    : "=r"(b[nq * 2][0]), "=r"(b[nq * 2][1]),
                      "=r"(b[nq * 2 + 1][0]), "=r"(b[nq * 2 + 1][1])
                    : "r"(ad));
            }
            #pragma unroll
            for (int mf = 0; mf < 2; mf++)
                #pragma unroll
                for (int nf = 0; nf < 8; nf++)
                    asm volatile(
                        "mma.sync.aligned.m16n8k16.row.col.f32.f16.f16.f32 "
                        "{%0,%1,%2,%3}, {%4,%5,%6,%7}, {%8,%9}, {%0,%1,%2,%3};"
                        : "+f"(c[mf][nf][0]), "+f"(c[mf][nf][1]),
                          "+f"(c[mf][nf][2]), "+f"(c[mf][nf][3])
                        : "r"(a[mf][0]), "r"(a[mf][1]), "r"(a[mf][2]), "r"(a[mf][3]),
                          "r"(b[nf][0]), "r"(b[nf][1]));
        }
    };

    // prologue: stages 0..ST-2 in flight
    #pragma unroll
    for (int s = 0; s < ST - 1; s++) issue(s);

    #pragma unroll
    for (int it = 0; it < KT; it++) {
        asm volatile("cp.async.wait_group %0;" :: "n"(ST - 2));  // stage it resident
        __syncthreads();                   // data visible + all warps done w/ stage it-1
        if (it + ST - 1 < KT) issue(it + ST - 1);  // overwrites buf (it-1)%ST: safe
        compute(it % ST);
    }

    // ---- store C ----
    #pragma unroll
    for (int mf = 0; mf < 2; mf++) {
        #pragma unroll
        for (int nf = 0; nf < 8; nf++) {
            int col = colBase + wn * 64 + nf * 8 + tg * 2;
            int r0 = rowBase + wm * 32 + mf * 16 + g;
            if (r0 < M)
                *(half2*)&C[(size_t)r0 * ND + col] = __floats2half2_rn(c[mf][nf][0], c[mf][nf][1]);
            int r1 = r0 + 8;
            if (r1 < M)
                *(half2*)&C[(size_t)r1 * ND + col] = __floats2half2_rn(c[mf][nf][2], c[mf][nf][3]);
        }
    }

    // ---- fused attention logits ----
    constexpr int NFH = CH / 8;            // nf per head (8 or 4)
    constexpr int NHW = 8 / NFH;           // heads per warp tile (1 or 2)
    const int headBase = (colBase + wn * 64) / CH;
    float asv[8][2], adv[8][2];
    #pragma unroll
    for (int nf = 0; nf < 8; nf++) {
        int hl  = nf / NFH;
        int cih = (nf % NFH) * 8 + tg * 2;
        int idx = (headBase + hl) * CH + cih;
        asv[nf][0] = att_s[idx];     asv[nf][1] = att_s[idx + 1];
        adv[nf][0] = att_d[idx];     adv[nf][1] = att_d[idx + 1];
    }
    #pragma unroll
    for (int mf = 0; mf < 2; mf++) {
        float ps0[NHW], pd0[NHW], ps1[NHW], pd1[NHW];
        #pragma unroll
        for (int hl = 0; hl < NHW; hl++) { ps0[hl] = pd0[hl] = ps1[hl] = pd1[hl] = 0.f; }
        #pragma unroll
        for (int nf = 0; nf < 8; nf++) {
            int hl = nf / NFH;
            ps0[hl] += c[mf][nf][0] * asv[nf][0] + c[mf][nf][1] * asv[nf][1];
            pd0[hl] += c[mf][nf][0] * adv[nf][0] + c[mf][nf][1] * adv[nf][1];
            ps1[hl] += c[mf][nf][2] * asv[nf][0] + c[mf][nf][3] * asv[nf][1];
            pd1[hl] += c[mf][nf][2] * adv[nf][0] + c[mf][nf][3] * adv[nf][1];
        }
        int r0 = rowBase + wm * 32 + mf * 16 + g;
        int r1 = r0 + 8;
        #pragma unroll
        for (int hl = 0; hl < NHW; hl++) {
            #pragma unroll
            for (int o = 1; o <= 2; o <<= 1) {
                ps0[hl] += __shfl_xor_sync(0xFFFFFFFFu, ps0[hl], o);
                pd0[hl] += __shfl_xor_sync(0xFFFFFFFFu, pd0[hl], o);
                ps1[hl] += __shfl_xor_sync(0xFFFFFFFFu, ps1[hl], o);
                pd1[hl] += __shfl_xor_sync(0xFFFFFFFFu, pd1[hl], o);
            }
            if (tg == 0) {
                int hg = headBase + hl;
                if (r0 < M) { asrc[r0 * 8 + hg] = ps0[hl]; adst[r0 * 8 + hg] = pd0[hl]; }
                if (r1 < M) { asrc[r1 * 8 + hg] = ps1[hl]; adst[r1 * 8 + hg] = pd1[hl]; }
            }
        }
    }
}

// smem bytes for the pipeline (host-side mirror of kernel constants)
constexpr int gemm_smem_bytes(int KT) {
    int st = (KT >= 3) ? 3 : 2;
    return st * (128 * (32 + 8) + 32 * (128 + 8)) * (int)sizeof(__half);
}

// ---------------- GAT aggregation: single-pass unnormalized softmax ----------------
// alpha = exp(e)/sum(exp(e)) (no max-sub; |e| small). Accumulate unnormalized,
// track per-head denominator, scale at end. One block per dst node, 256 threads.
// uint4 gathers (8 channels/thread): TPE = CH threads/edge, EPB = 256/CH edges
// in flight per inner step.
template<int CH, typename OutT>
__global__ __launch_bounds__(256)
void gat_aggregate_kernel(const __half* __restrict__ h,
                          const float* __restrict__ asrc,
                          const float* __restrict__ adst,
                          const float* __restrict__ bias,
                          OutT* __restrict__ out,
                          int do_relu) {
    constexpr int NT   = 256;
    constexpr int CK   = 256;              // chunk size
    constexpr int TPE  = CH;               // threads per edge (row = CH uint4)
    constexpr int EPB  = NT / TPE;         // edges in parallel (4 or 8)
    constexpr int TPH  = CH / 8;           // threads per head (8 or 4)
    const int d = blockIdx.x;
    const int t = threadIdx.x;
    const int start = g_off[d];
    const int deg = g_off[d + 1] - start;

    __shared__ float sm_adst[8], sm_is[8];
    __shared__ int   s_src[CK];
    __shared__ float s_w[CK * 8];
    __shared__ float s_dp[NT];
    __shared__ float s_red[EPB][8][CH];

    if (t < 8) sm_adst[t] = adst[d * 8 + t];
    __syncthreads();

    const int sub = t / TPE;               // which edge of the group
    const int rr  = t % TPE;
    const int hh  = rr / TPH;              // head
    const int co  = rr % TPH;              // uint4 index within head (8 channels)
    const uint4* __restrict__ h8p = (const uint4*)h;
    float acc[8] = {0.f, 0.f, 0.f, 0.f, 0.f, 0.f, 0.f, 0.f};
    float denp = 0.f;

    for (int base = 0; base < deg; base += CK) {
        const int cnt = min(CK, deg - base);
        if (t < cnt) s_src[t] = g_csr[start + base + t];
        __syncthreads();
        // weights: entry idx -> edge idx>>3, head idx&7
        for (int idx = t; idx < cnt * 8; idx += NT) {
            int j = idx >> 3, h2 = idx & 7;
            int s = s_src[j];
            float e = asrc[s * 8 + h2] + sm_adst[h2];
            e = (e > 0.f) ? e : NEG_SLOPE * e;
            float w = __expf(e);
            s_w[idx] = w;
            denp += w;
        }
        __syncthreads();
        #pragma unroll 4
        for (int j = sub; j < cnt; j += EPB) {
            float w = s_w[j * 8 + hh];
            uint4 raw = h8p[(size_t)s_src[j] * CH + hh * TPH + co];
            float2 v0 = __half22float2(*(const half2*)&raw.x);
            float2 v1 = __half22float2(*(const half2*)&raw.y);
            float2 v2 = __half22float2(*(const half2*)&raw.z);
            float2 v3 = __half22float2(*(const half2*)&raw.w);
            acc[0] = fmaf(w, v0.x, acc[0]);
            acc[1] = fmaf(w, v0.y, acc[1]);
            acc[2] = fmaf(w, v1.x, acc[2]);
            acc[3] = fmaf(w, v1.y, acc[3]);
            acc[4] = fmaf(w, v2.x, acc[4]);
            acc[5] = fmaf(w, v2.y, acc[5]);
            acc[6] = fmaf(w, v3.x, acc[6]);
            acc[7] = fmaf(w, v3.y, acc[7]);
        }
        __syncthreads();
    }

    // reduce per-head denominators (thread t contributed to head t&7)
    s_dp[t] = denp;
    __syncthreads();
    if (t < 8) {
        float tot = 0.f;
        #pragma unroll
        for (int k = t; k < NT; k += 8) tot += s_dp[k];
        sm_is[t] = 1.0f / tot;
    }
    __syncthreads();

    const float is = sm_is[hh];
    *(float4*)&s_red[sub][hh][co * 8]     = make_float4(acc[0] * is, acc[1] * is,
                                                        acc[2] * is, acc[3] * is);
    *(float4*)&s_red[sub][hh][co * 8 + 4] = make_float4(acc[4] * is, acc[5] * is,
                                                        acc[6] * is, acc[7] * is);
    __syncthreads();
    if (t < CH) {
        float v = 0.f;
        #pragma unroll
        for (int sb = 0; sb < EPB; sb++)
            #pragma unroll
            for (int k = 0; k < 8; k++) v += s_red[sb][k][t];
        v = v * 0.125f + bias[t];
        if (do_relu) v = fmaxf(v, 0.f);
        if constexpr (sizeof(OutT) == 2)
            out[(size_t)d * CH + t] = __float2half(v);
        else
            out[(size_t)d * CH + t] = v;
    }
}

// ---------------- launch ----------------
extern "C" void kernel_launch(void* const* d_in, const int* in_sizes, int n_in,
                              void* d_out, int out_size) {
    const float* x    = (const float*)d_in[0];
    const int*   ei   = (const int*)  d_in[1];
    const float* W1   = (const float*)d_in[2];
    const float* as1  = (const float*)d_in[3];
    const float* ad1  = (const float*)d_in[4];
    const float* b1   = (const float*)d_in[5];
    const float* W2   = (const float*)d_in[6];
    const float* as2  = (const float*)d_in[7];
    const float* ad2  = (const float*)d_in[8];
    const float* b2   = (const float*)d_in[9];
    float* out = (float*)d_out;

    __half *p_xh, *p_W1h, *p_W2h, *p_h1, *p_hmid, *p_h2;
    float *p_as1, *p_ad1, *p_as2, *p_ad2;
    int *p_deg;
    cudaGetSymbolAddress((void**)&p_xh,   g_xh);
    cudaGetSymbolAddress((void**)&p_W1h,  g_W1h);
    cudaGetSymbolAddress((void**)&p_W2h,  g_W2h);
    cudaGetSymbolAddress((void**)&p_h1,   g_h1);
    cudaGetSymbolAddress((void**)&p_hmid, g_hmid);
    cudaGetSymbolAddress((void**)&p_h2,   g_h2);
    cudaGetSymbolAddress((void**)&p_as1,  g_as1);
    cudaGetSymbolAddress((void**)&p_ad1,  g_ad1);
    cudaGetSymbolAddress((void**)&p_as2,  g_as2);
    cudaGetSymbolAddress((void**)&p_ad2,  g_ad2);
    cudaGetSymbolAddress((void**)&p_deg,  g_deg);

    // dynamic-smem opt-in for the 3-stage GEMM1 (>48KB); host attr call, capture-safe
    constexpr int SM1 = gemm_smem_bytes(INF_C / 32);   // 3 stages
    constexpr int SM2 = gemm_smem_bytes(HF1 / 32);     // 2 stages
    cudaFuncSetAttribute(h16_gemm_kernel<INF_C, HEADS * HF1, HF1>,
                         cudaFuncAttributeMaxDynamicSharedMemorySize, SM1);
    cudaFuncSetAttribute(h16_gemm_kernel<HF1, HEADS * OUT2, OUT2>,
                         cudaFuncAttributeMaxDynamicSharedMemorySize, SM2);

    // CSR + fp16 prep
    cudaMemsetAsync(p_deg, 0, NN * sizeof(int));
    constexpr int PREP_ITEMS = NN * INF_C / 4 + INF_C * HEADS * HF1 / 4
                             + HF1 * HEADS * OUT2 / 4 + EE;
    prep_kernel<<<(PREP_ITEMS + 255) / 256, 256>>>(x, W1, W2, ei);
    scan_kernel<<<1, 1024>>>();
    fill_csr_kernel<<<(ETOT + 255) / 256, 256>>>(ei);

    // GEMM1 + logits1
    {
        dim3 grid((HEADS * HF1) / 128, (NN + 127) / 128);
        h16_gemm_kernel<INF_C, HEADS * HF1, HF1><<<grid, 256, SM1>>>(
            NN, p_xh, p_W1h, p_h1, as1, ad1, p_as1, p_ad1);
    }
    // aggregation 1
    gat_aggregate_kernel<HF1, __half><<<NN, 256>>>(p_h1, p_as1, p_ad1, b1, p_hmid, 1);

    // GEMM2 + logits2
    {
        dim3 grid((HEADS * OUT2) / 128, (NN + 127) / 128);
        h16_gemm_kernel<HF1, HEADS * OUT2, OUT2><<<grid, 256, SM2>>>(
            NN, p_hmid, p_W2h, p_h2, as2, ad2, p_as2, p_ad2);
    }
    // aggregation 2
    gat_aggregate_kernel<OUT2, float><<<NN, 256>>>(p_h2, p_as2, p_ad2, b2, out, 0);
}